// round 1
// baseline (speedup 1.0000x reference)
#include <cuda_runtime.h>
#include <math.h>

#define BATCH   32
#define SEQ     577
#define CDIM    1024
#define HDIM    4096
#define NHEADS  16
#define DH      64
#define ROWS    (BATCH * SEQ)          // 18464

// ---------------- scratch (static device globals; no runtime allocation) ----
__device__ float g_h  [(size_t)ROWS * CDIM];      // LN output (reused ln1/ln2)
__device__ float g_qkv[(size_t)ROWS * 3 * CDIM];  // QKV
__device__ float g_o  [(size_t)ROWS * CDIM];      // attention output (head-merged)
__device__ float g_x1 [(size_t)ROWS * CDIM];      // x + proj
__device__ float g_mid[(size_t)ROWS * HDIM];      // gelu(fc1)

// ---------------- LayerNorm: one block per row, 256 threads, float4 ---------
__global__ void ln_kernel(const float* __restrict__ x,
                          const float* __restrict__ w,
                          const float* __restrict__ b,
                          float* __restrict__ out) {
    __shared__ float red[16];
    int row = blockIdx.x;
    int t = threadIdx.x;
    const float4* xr = (const float4*)(x + (size_t)row * CDIM);
    float4 v = xr[t];
    float s  = v.x + v.y + v.z + v.w;
    float ss = v.x*v.x + v.y*v.y + v.z*v.z + v.w*v.w;
    #pragma unroll
    for (int m = 16; m; m >>= 1) {
        s  += __shfl_xor_sync(0xffffffffu, s,  m);
        ss += __shfl_xor_sync(0xffffffffu, ss, m);
    }
    int warp = t >> 5;
    if ((t & 31) == 0) { red[warp] = s; red[warp + 8] = ss; }
    __syncthreads();
    s = 0.f; ss = 0.f;
    #pragma unroll
    for (int i = 0; i < 8; i++) { s += red[i]; ss += red[i + 8]; }
    float mean = s * (1.0f / CDIM);
    float var  = ss * (1.0f / CDIM) - mean * mean;
    float inv  = rsqrtf(var + 1e-6f);
    float4 wv = ((const float4*)w)[t];
    float4 bv = ((const float4*)b)[t];
    float4 o;
    o.x = (v.x - mean) * inv * wv.x + bv.x;
    o.y = (v.y - mean) * inv * wv.y + bv.y;
    o.z = (v.z - mean) * inv * wv.z + bv.z;
    o.w = (v.w - mean) * inv * wv.w + bv.w;
    ((float4*)(out + (size_t)row * CDIM))[t] = o;
}

// ---------------- GEMM: C[m][n] = sum_k A[m][k]*B[n][k] + epilogue ----------
// EPI: 0 = +bias, 1 = +bias+res, 2 = +bias then exact GELU
template<int EPI>
__global__ __launch_bounds__(256, 2)
void gemm_kernel(const float* __restrict__ A, const float* __restrict__ B,
                 const float* __restrict__ bias, const float* __restrict__ res,
                 float* __restrict__ C, int M, int N, int K) {
    __shared__ float As[16][132];
    __shared__ float Bs[16][132];
    int tid = threadIdx.x;
    int bm = blockIdx.y * 128;
    int bn = blockIdx.x * 128;
    int tx = tid & 15, ty = tid >> 4;

    float acc[8][8];
    #pragma unroll
    for (int i = 0; i < 8; i++)
        #pragma unroll
        for (int j = 0; j < 8; j++) acc[i][j] = 0.f;

    for (int k0 = 0; k0 < K; k0 += 16) {
        // load A tile (guard M edge) and B tile, transposed into smem
        #pragma unroll
        for (int l = 0; l < 2; l++) {
            int idx = tid + l * 256;
            int rrow = idx >> 2, kq = (idx & 3) * 4;
            int gr = bm + rrow;
            float4 av = make_float4(0.f, 0.f, 0.f, 0.f);
            if (gr < M) av = *(const float4*)&A[(size_t)gr * K + k0 + kq];
            As[kq + 0][rrow] = av.x; As[kq + 1][rrow] = av.y;
            As[kq + 2][rrow] = av.z; As[kq + 3][rrow] = av.w;
            int gb = bn + rrow;
            float4 bvv = *(const float4*)&B[(size_t)gb * K + k0 + kq];
            Bs[kq + 0][rrow] = bvv.x; Bs[kq + 1][rrow] = bvv.y;
            Bs[kq + 2][rrow] = bvv.z; Bs[kq + 3][rrow] = bvv.w;
        }
        __syncthreads();
        #pragma unroll
        for (int k = 0; k < 16; k++) {
            float a[8], bb[8];
            *(float4*)(a)     = *(float4*)&As[k][ty * 8];
            *(float4*)(a + 4) = *(float4*)&As[k][ty * 8 + 4];
            *(float4*)(bb)     = *(float4*)&Bs[k][tx * 8];
            *(float4*)(bb + 4) = *(float4*)&Bs[k][tx * 8 + 4];
            #pragma unroll
            for (int i = 0; i < 8; i++)
                #pragma unroll
                for (int j = 0; j < 8; j++)
                    acc[i][j] += a[i] * bb[j];
        }
        __syncthreads();
    }

    // epilogue
    #pragma unroll
    for (int i = 0; i < 8; i++) {
        int gr = bm + ty * 8 + i;
        if (gr >= M) break;
        size_t rowoff = (size_t)gr * N + bn + tx * 8;
        #pragma unroll
        for (int jj = 0; jj < 8; jj += 4) {
            float4 bv = *(const float4*)&bias[bn + tx * 8 + jj];
            float4 vv;
            vv.x = acc[i][jj + 0] + bv.x;
            vv.y = acc[i][jj + 1] + bv.y;
            vv.z = acc[i][jj + 2] + bv.z;
            vv.w = acc[i][jj + 3] + bv.w;
            if (EPI == 1) {
                float4 rv = *(const float4*)&res[rowoff + jj];
                vv.x += rv.x; vv.y += rv.y; vv.z += rv.z; vv.w += rv.w;
            }
            if (EPI == 2) {
                vv.x = 0.5f * vv.x * (1.f + erff(vv.x * 0.70710678118654752f));
                vv.y = 0.5f * vv.y * (1.f + erff(vv.y * 0.70710678118654752f));
                vv.z = 0.5f * vv.z * (1.f + erff(vv.z * 0.70710678118654752f));
                vv.w = 0.5f * vv.w * (1.f + erff(vv.w * 0.70710678118654752f));
            }
            *(float4*)&C[rowoff + jj] = vv;
        }
    }
}

// ---------------- fused attention (flash-style, online softmax) -------------
// grid (B*H, ceil(SEQ/64)), 256 threads. smem: QsT/KsT/Vs/Ps each [64][68].
#define SMP 68
__global__ __launch_bounds__(256)
void attn_kernel(const float* __restrict__ qkv, float* __restrict__ o) {
    extern __shared__ float sm[];
    float* QsT = sm;                 // [d][r] (k-major)
    float* KsT = sm + 64 * SMP;      // [d][c]
    float* Vs  = sm + 2 * 64 * SMP;  // [c][d]
    float* Ps  = sm + 3 * 64 * SMP;  // [r][c]

    int bh = blockIdx.x;
    int b = bh >> 4, h = bh & 15;
    int q0 = blockIdx.y * 64;
    int tid = threadIdx.x;
    int tx = tid & 15, ty = tid >> 4;

    // load Q tile transposed, pre-scaled
    for (int i = tid; i < 1024; i += 256) {
        int r = i >> 4, d4 = (i & 15) * 4;
        int qr = q0 + r;
        float4 v = make_float4(0.f, 0.f, 0.f, 0.f);
        if (qr < SEQ)
            v = *(const float4*)&qkv[(size_t)(b * SEQ + qr) * 3072 + h * 64 + d4];
        QsT[(d4 + 0) * SMP + r] = v.x * 0.125f;
        QsT[(d4 + 1) * SMP + r] = v.y * 0.125f;
        QsT[(d4 + 2) * SMP + r] = v.z * 0.125f;
        QsT[(d4 + 3) * SMP + r] = v.w * 0.125f;
    }

    float m[4], l[4], acc[4][4];
    #pragma unroll
    for (int i = 0; i < 4; i++) {
        m[i] = -1e30f; l[i] = 0.f;
        #pragma unroll
        for (int j = 0; j < 4; j++) acc[i][j] = 0.f;
    }

    for (int kt = 0; kt < 10; kt++) {
        int k0 = kt * 64;
        __syncthreads();   // previous O phase done reading Vs/Ps
        for (int i = tid; i < 1024; i += 256) {
            int c = i >> 4, d4 = (i & 15) * 4;
            int kr = k0 + c;
            float4 kv = make_float4(0.f, 0.f, 0.f, 0.f);
            float4 vv = make_float4(0.f, 0.f, 0.f, 0.f);
            if (kr < SEQ) {
                size_t base = (size_t)(b * SEQ + kr) * 3072 + h * 64 + d4;
                kv = *(const float4*)&qkv[base + 1024];
                vv = *(const float4*)&qkv[base + 2048];
            }
            KsT[(d4 + 0) * SMP + c] = kv.x;
            KsT[(d4 + 1) * SMP + c] = kv.y;
            KsT[(d4 + 2) * SMP + c] = kv.z;
            KsT[(d4 + 3) * SMP + c] = kv.w;
            *(float4*)&Vs[c * SMP + d4] = vv;
        }
        __syncthreads();

        // S = Q Kt (4x4 micro-tile, outer-product over d)
        float s[4][4];
        #pragma unroll
        for (int i = 0; i < 4; i++)
            #pragma unroll
            for (int j = 0; j < 4; j++) s[i][j] = 0.f;
        #pragma unroll 8
        for (int d = 0; d < 64; d++) {
            float qa[4], ka[4];
            *(float4*)qa = *(float4*)&QsT[d * SMP + ty * 4];
            *(float4*)ka = *(float4*)&KsT[d * SMP + tx * 4];
            #pragma unroll
            for (int i = 0; i < 4; i++)
                #pragma unroll
                for (int j = 0; j < 4; j++)
                    s[i][j] += qa[i] * ka[j];
        }
        // mask invalid keys
        #pragma unroll
        for (int j = 0; j < 4; j++)
            if (k0 + tx * 4 + j >= SEQ) {
                #pragma unroll
                for (int i = 0; i < 4; i++) s[i][j] = -1e30f;
            }
        // online softmax update (reduce across the 16 lanes sharing ty)
        #pragma unroll
        for (int i = 0; i < 4; i++) {
            float mx = fmaxf(fmaxf(s[i][0], s[i][1]), fmaxf(s[i][2], s[i][3]));
            #pragma unroll
            for (int msk = 8; msk; msk >>= 1)
                mx = fmaxf(mx, __shfl_xor_sync(0xffffffffu, mx, msk));
            float mnew = fmaxf(m[i], mx);
            float f = __expf(m[i] - mnew);
            float rs = 0.f;
            #pragma unroll
            for (int j = 0; j < 4; j++) {
                s[i][j] = __expf(s[i][j] - mnew);
                rs += s[i][j];
            }
            #pragma unroll
            for (int msk = 8; msk; msk >>= 1)
                rs += __shfl_xor_sync(0xffffffffu, rs, msk);
            l[i] = l[i] * f + rs;
            m[i] = mnew;
            #pragma unroll
            for (int j = 0; j < 4; j++) acc[i][j] *= f;
            *(float4*)&Ps[(ty * 4 + i) * SMP + tx * 4] =
                make_float4(s[i][0], s[i][1], s[i][2], s[i][3]);
        }
        __syncthreads();
        // O += P V
        #pragma unroll 8
        for (int c = 0; c < 64; c++) {
            float pa[4], va[4];
            pa[0] = Ps[(ty * 4 + 0) * SMP + c];
            pa[1] = Ps[(ty * 4 + 1) * SMP + c];
            pa[2] = Ps[(ty * 4 + 2) * SMP + c];
            pa[3] = Ps[(ty * 4 + 3) * SMP + c];
            *(float4*)va = *(float4*)&Vs[c * SMP + tx * 4];
            #pragma unroll
            for (int i = 0; i < 4; i++)
                #pragma unroll
                for (int j = 0; j < 4; j++)
                    acc[i][j] += pa[i] * va[j];
        }
    }

    // write O (head-merged [B,N,C] layout)
    #pragma unroll
    for (int i = 0; i < 4; i++) {
        int qr = q0 + ty * 4 + i;
        if (qr < SEQ) {
            float invl = 1.f / l[i];
            float4 ov = make_float4(acc[i][0] * invl, acc[i][1] * invl,
                                    acc[i][2] * invl, acc[i][3] * invl);
            *(float4*)&o[(size_t)(b * SEQ + qr) * CDIM + h * 64 + tx * 4] = ov;
        }
    }
}

// ---------------- orchestration ---------------------------------------------
extern "C" void kernel_launch(void* const* d_in, const int* in_sizes, int n_in,
                              void* d_out, int out_size) {
    const float* x      = (const float*)d_in[0];
    const float* ln1_w  = (const float*)d_in[1];
    const float* ln1_b  = (const float*)d_in[2];
    const float* qkv_w  = (const float*)d_in[3];
    const float* qkv_b  = (const float*)d_in[4];
    const float* proj_w = (const float*)d_in[5];
    const float* proj_b = (const float*)d_in[6];
    const float* ln2_w  = (const float*)d_in[7];
    const float* ln2_b  = (const float*)d_in[8];
    const float* fc1_w  = (const float*)d_in[9];
    const float* fc1_b  = (const float*)d_in[10];
    const float* fc2_w  = (const float*)d_in[11];
    const float* fc2_b  = (const float*)d_in[12];
    float* out = (float*)d_out;

    float *h, *qkvb, *ob, *x1, *mid;
    cudaGetSymbolAddress((void**)&h,    g_h);
    cudaGetSymbolAddress((void**)&qkvb, g_qkv);
    cudaGetSymbolAddress((void**)&ob,   g_o);
    cudaGetSymbolAddress((void**)&x1,   g_x1);
    cudaGetSymbolAddress((void**)&mid,  g_mid);

    const int gy = (ROWS + 127) / 128;   // 145

    // 1) LN1
    ln_kernel<<<ROWS, 256>>>(x, ln1_w, ln1_b, h);
    // 2) QKV GEMM: [18464,1024] x [3072,1024]^T
    gemm_kernel<0><<<dim3(3 * CDIM / 128, gy), 256>>>(h, qkv_w, qkv_b, nullptr,
                                                      qkvb, ROWS, 3 * CDIM, CDIM);
    // 3) fused attention
    int smem = 4 * 64 * SMP * sizeof(float);
    cudaFuncSetAttribute(attn_kernel, cudaFuncAttributeMaxDynamicSharedMemorySize, smem);
    attn_kernel<<<dim3(BATCH * NHEADS, (SEQ + 63) / 64), 256, smem>>>(qkvb, ob);
    // 4) proj + residual(x)
    gemm_kernel<1><<<dim3(CDIM / 128, gy), 256>>>(ob, proj_w, proj_b, x,
                                                  x1, ROWS, CDIM, CDIM);
    // 5) LN2
    ln_kernel<<<ROWS, 256>>>(x1, ln2_w, ln2_b, h);
    // 6) fc1 + exact GELU
    gemm_kernel<2><<<dim3(HDIM / 128, gy), 256>>>(h, fc1_w, fc1_b, nullptr,
                                                  mid, ROWS, HDIM, CDIM);
    // 7) fc2 + residual(x1) -> out
    gemm_kernel<1><<<dim3(CDIM / 128, gy), 256>>>(mid, fc2_w, fc2_b, x1,
                                                  out, ROWS, CDIM, HDIM);
}

// round 4
// speedup vs baseline: 1.9785x; 1.9785x over previous
#include <cuda_runtime.h>
#include <cuda_bf16.h>
#include <math.h>

#define BATCH   32
#define SEQ     577
#define CDIM    1024
#define HDIM    4096
#define NHEADS  16
#define ROWS    (BATCH * SEQ)          // 18464

// ---------------- scratch (static device globals; no runtime allocation) ----
__device__ float g_h  [(size_t)ROWS * CDIM];
__device__ float g_qkv[(size_t)ROWS * 3 * CDIM];
__device__ float g_o  [(size_t)ROWS * CDIM];
__device__ float g_x1 [(size_t)ROWS * CDIM];
__device__ float g_mid[(size_t)ROWS * HDIM];

// ---------------- LayerNorm ---------------------------------------------------
__global__ void ln_kernel(const float* __restrict__ x,
                          const float* __restrict__ w,
                          const float* __restrict__ b,
                          float* __restrict__ out) {
    __shared__ float red[16];
    int row = blockIdx.x;
    int t = threadIdx.x;
    const float4* xr = (const float4*)(x + (size_t)row * CDIM);
    float4 v = xr[t];
    float s  = v.x + v.y + v.z + v.w;
    float ss = v.x*v.x + v.y*v.y + v.z*v.z + v.w*v.w;
    #pragma unroll
    for (int m = 16; m; m >>= 1) {
        s  += __shfl_xor_sync(0xffffffffu, s,  m);
        ss += __shfl_xor_sync(0xffffffffu, ss, m);
    }
    int warp = t >> 5;
    if ((t & 31) == 0) { red[warp] = s; red[warp + 8] = ss; }
    __syncthreads();
    s = 0.f; ss = 0.f;
    #pragma unroll
    for (int i = 0; i < 8; i++) { s += red[i]; ss += red[i + 8]; }
    float mean = s * (1.0f / CDIM);
    float var  = ss * (1.0f / CDIM) - mean * mean;
    float inv  = rsqrtf(var + 1e-6f);
    float4 wv = ((const float4*)w)[t];
    float4 bv = ((const float4*)b)[t];
    float4 o;
    o.x = (v.x - mean) * inv * wv.x + bv.x;
    o.y = (v.y - mean) * inv * wv.y + bv.y;
    o.z = (v.z - mean) * inv * wv.z + bv.z;
    o.w = (v.w - mean) * inv * wv.w + bv.w;
    ((float4*)(out + (size_t)row * CDIM))[t] = o;
}

// ---------------- tensor-core GEMM helpers -----------------------------------
__device__ __forceinline__ unsigned smem_u32(const void* p) {
    return (unsigned)__cvta_generic_to_shared(p);
}
__device__ __forceinline__ void ldm_x4(unsigned* r, unsigned addr) {
    asm volatile("ldmatrix.sync.aligned.m8n8.x4.shared.b16 {%0,%1,%2,%3}, [%4];\n"
                 : "=r"(r[0]), "=r"(r[1]), "=r"(r[2]), "=r"(r[3]) : "r"(addr));
}
__device__ __forceinline__ void mma16816(float* c, const unsigned* a, const unsigned* b) {
    asm volatile("mma.sync.aligned.m16n8k16.row.col.f32.bf16.bf16.f32 "
                 "{%0,%1,%2,%3},{%4,%5,%6,%7},{%8,%9},{%0,%1,%2,%3};\n"
                 : "+f"(c[0]), "+f"(c[1]), "+f"(c[2]), "+f"(c[3])
                 : "r"(a[0]), "r"(a[1]), "r"(a[2]), "r"(a[3]), "r"(b[0]), "r"(b[1]));
}

#define SPAD 40   // bf16 per smem row (32 data + 8 pad): 80B stride, ldmatrix conflict-free

// C[m][n] = sum_k A[m][k]*B[n][k] + epilogue.  EPI: 0=+bias, 1=+bias+res, 2=+bias+GELU
template<int EPI>
__global__ __launch_bounds__(256, 1)
void gemm_tc(const float* __restrict__ A, const float* __restrict__ B,
             const float* __restrict__ bias, const float* __restrict__ res,
             float* __restrict__ C, int M, int N, int K) {
    __shared__ __nv_bfloat16 Ah[128][SPAD], Al[128][SPAD];
    __shared__ __nv_bfloat16 Bh[128][SPAD], Bl[128][SPAD];

    int tid  = threadIdx.x;
    int lane = tid & 31;
    int warp = tid >> 5;
    int wm = warp >> 2;           // 0..1
    int wn = warp & 3;            // 0..3
    int bm = blockIdx.y * 128;
    int bn = blockIdx.x * 128;

    float c[4][4][4];
    #pragma unroll
    for (int i = 0; i < 4; i++)
        #pragma unroll
        for (int j = 0; j < 4; j++)
            #pragma unroll
            for (int r = 0; r < 4; r++) c[i][j][r] = 0.f;

    float4 pa[4], pb[4];
    const float4 z4 = make_float4(0.f, 0.f, 0.f, 0.f);

    // prefetch first tile
    #pragma unroll
    for (int l2 = 0; l2 < 4; l2++) {
        int flat = tid + (l2 << 8);
        int row = flat >> 3, kq = (flat & 7) << 2;
        int gr = bm + row;
        pa[l2] = (gr < M) ? *(const float4*)&A[(size_t)gr * K + kq] : z4;
        pb[l2] = *(const float4*)&B[(size_t)(bn + row) * K + kq];
    }

    for (int k0 = 0; k0 < K; k0 += 32) {
        // convert prefetched tile to bf16 hi/lo and store to smem
        #pragma unroll
        for (int l2 = 0; l2 < 4; l2++) {
            int flat = tid + (l2 << 8);
            int row = flat >> 3, kq = (flat & 7) << 2;
            float fa[4] = {pa[l2].x, pa[l2].y, pa[l2].z, pa[l2].w};
            float fb[4] = {pb[l2].x, pb[l2].y, pb[l2].z, pb[l2].w};
            __nv_bfloat16 ha[4], la[4], hb[4], lb[4];
            #pragma unroll
            for (int q = 0; q < 4; q++) {
                ha[q] = __float2bfloat16(fa[q]);
                la[q] = __float2bfloat16(fa[q] - __bfloat162float(ha[q]));
                hb[q] = __float2bfloat16(fb[q]);
                lb[q] = __float2bfloat16(fb[q] - __bfloat162float(hb[q]));
            }
            *(__nv_bfloat162*)&Ah[row][kq]     = __nv_bfloat162(ha[0], ha[1]);
            *(__nv_bfloat162*)&Ah[row][kq + 2] = __nv_bfloat162(ha[2], ha[3]);
            *(__nv_bfloat162*)&Al[row][kq]     = __nv_bfloat162(la[0], la[1]);
            *(__nv_bfloat162*)&Al[row][kq + 2] = __nv_bfloat162(la[2], la[3]);
            *(__nv_bfloat162*)&Bh[row][kq]     = __nv_bfloat162(hb[0], hb[1]);
            *(__nv_bfloat162*)&Bh[row][kq + 2] = __nv_bfloat162(hb[2], hb[3]);
            *(__nv_bfloat162*)&Bl[row][kq]     = __nv_bfloat162(lb[0], lb[1]);
            *(__nv_bfloat162*)&Bl[row][kq + 2] = __nv_bfloat162(lb[2], lb[3]);
        }
        __syncthreads();

        // prefetch next tile (LDGs overlap with MMA phase)
        if (k0 + 32 < K) {
            #pragma unroll
            for (int l2 = 0; l2 < 4; l2++) {
                int flat = tid + (l2 << 8);
                int row = flat >> 3, kq = (flat & 7) << 2;
                int gr = bm + row;
                pa[l2] = (gr < M) ? *(const float4*)&A[(size_t)gr * K + k0 + 32 + kq] : z4;
                pb[l2] = *(const float4*)&B[(size_t)(bn + row) * K + k0 + 32 + kq];
            }
        }

        #pragma unroll
        for (int kk = 0; kk < 2; kk++) {
            int ki = kk << 4;
            unsigned ah[4][4], al[4][4];
            #pragma unroll
            for (int i = 0; i < 4; i++) {
                int arow = wm * 64 + i * 16 + (lane & 15);
                int acol = ki + ((lane >> 4) << 3);
                ldm_x4(ah[i], smem_u32(&Ah[arow][acol]));
                ldm_x4(al[i], smem_u32(&Al[arow][acol]));
            }
            unsigned bh[4][2], bl[4][2];
            #pragma unroll
            for (int jp = 0; jp < 2; jp++) {
                int brow = wn * 32 + jp * 16 + (((lane >> 4) & 1) << 3) + (lane & 7);
                int bcol = ki + (((lane >> 3) & 1) << 3);
                unsigned t4[4];
                ldm_x4(t4, smem_u32(&Bh[brow][bcol]));
                bh[2*jp][0] = t4[0]; bh[2*jp][1] = t4[1];
                bh[2*jp+1][0] = t4[2]; bh[2*jp+1][1] = t4[3];
                ldm_x4(t4, smem_u32(&Bl[brow][bcol]));
                bl[2*jp][0] = t4[0]; bl[2*jp][1] = t4[1];
                bl[2*jp+1][0] = t4[2]; bl[2*jp+1][1] = t4[3];
            }
            #pragma unroll
            for (int i = 0; i < 4; i++)
                #pragma unroll
                for (int j = 0; j < 4; j++) {
                    mma16816(c[i][j], ah[i], bh[j]);
                    mma16816(c[i][j], ah[i], bl[j]);
                    mma16816(c[i][j], al[i], bh[j]);
                }
        }
        __syncthreads();
    }

    // epilogue
    int g = lane >> 2, t2 = (lane & 3) << 1;
    #pragma unroll
    for (int i = 0; i < 4; i++) {
        #pragma unroll
        for (int j = 0; j < 4; j++) {
            int cc = bn + wn * 32 + j * 8 + t2;
            float2 bv = *(const float2*)&bias[cc];
            #pragma unroll
            for (int half = 0; half < 2; half++) {
                int gr = bm + wm * 64 + i * 16 + g + half * 8;
                if (gr < M) {
                    float2 vv;
                    vv.x = c[i][j][half * 2 + 0] + bv.x;
                    vv.y = c[i][j][half * 2 + 1] + bv.y;
                    size_t off = (size_t)gr * N + cc;
                    if (EPI == 1) {
                        float2 rv = *(const float2*)&res[off];
                        vv.x += rv.x; vv.y += rv.y;
                    }
                    if (EPI == 2) {
                        vv.x = 0.5f * vv.x * (1.f + erff(vv.x * 0.70710678118654752f));
                        vv.y = 0.5f * vv.y * (1.f + erff(vv.y * 0.70710678118654752f));
                    }
                    *(float2*)&C[off] = vv;
                }
            }
        }
    }
}

// ---------------- fused attention (flash-style, fp32 SIMT) ------------------
#define SMP 68
__global__ __launch_bounds__(256)
void attn_kernel(const float* __restrict__ qkv, float* __restrict__ o) {
    extern __shared__ float sm[];
    float* QsT = sm;
    float* KsT = sm + 64 * SMP;
    float* Vs  = sm + 2 * 64 * SMP;
    float* Ps  = sm + 3 * 64 * SMP;

    int bh = blockIdx.x;
    int b = bh >> 4, h = bh & 15;
    int q0 = blockIdx.y * 64;
    int tid = threadIdx.x;
    int tx = tid & 15, ty = tid >> 4;

    for (int i = tid; i < 1024; i += 256) {
        int r = i >> 4, d4 = (i & 15) * 4;
        int qr = q0 + r;
        float4 v = make_float4(0.f, 0.f, 0.f, 0.f);
        if (qr < SEQ)
            v = *(const float4*)&qkv[(size_t)(b * SEQ + qr) * 3072 + h * 64 + d4];
        QsT[(d4 + 0) * SMP + r] = v.x * 0.125f;
        QsT[(d4 + 1) * SMP + r] = v.y * 0.125f;
        QsT[(d4 + 2) * SMP + r] = v.z * 0.125f;
        QsT[(d4 + 3) * SMP + r] = v.w * 0.125f;
    }

    float m[4], l[4], acc[4][4];
    #pragma unroll
    for (int i = 0; i < 4; i++) {
        m[i] = -1e30f; l[i] = 0.f;
        #pragma unroll
        for (int j = 0; j < 4; j++) acc[i][j] = 0.f;
    }

    for (int kt = 0; kt < 10; kt++) {
        int k0 = kt * 64;
        __syncthreads();
        for (int i = tid; i < 1024; i += 256) {
            int cc = i >> 4, d4 = (i & 15) * 4;
            int kr = k0 + cc;
            float4 kv = make_float4(0.f, 0.f, 0.f, 0.f);
            float4 vv = make_float4(0.f, 0.f, 0.f, 0.f);
            if (kr < SEQ) {
                size_t base = (size_t)(b * SEQ + kr) * 3072 + h * 64 + d4;
                kv = *(const float4*)&qkv[base + 1024];
                vv = *(const float4*)&qkv[base + 2048];
            }
            KsT[(d4 + 0) * SMP + cc] = kv.x;
            KsT[(d4 + 1) * SMP + cc] = kv.y;
            KsT[(d4 + 2) * SMP + cc] = kv.z;
            KsT[(d4 + 3) * SMP + cc] = kv.w;
            *(float4*)&Vs[cc * SMP + d4] = vv;
        }
        __syncthreads();

        float s[4][4];
        #pragma unroll
        for (int i = 0; i < 4; i++)
            #pragma unroll
            for (int j = 0; j < 4; j++) s[i][j] = 0.f;
        #pragma unroll 8
        for (int d = 0; d < 64; d++) {
            float qa[4], ka[4];
            *(float4*)qa = *(float4*)&QsT[d * SMP + ty * 4];
            *(float4*)ka = *(float4*)&KsT[d * SMP + tx * 4];
            #pragma unroll
            for (int i = 0; i < 4; i++)
                #pragma unroll
                for (int j = 0; j < 4; j++)
                    s[i][j] += qa[i] * ka[j];
        }
        #pragma unroll
        for (int j = 0; j < 4; j++)
            if (k0 + tx * 4 + j >= SEQ) {
                #pragma unroll
                for (int i = 0; i < 4; i++) s[i][j] = -1e30f;
            }
        #pragma unroll
        for (int i = 0; i < 4; i++) {
            float mx = fmaxf(fmaxf(s[i][0], s[i][1]), fmaxf(s[i][2], s[i][3]));
            #pragma unroll
            for (int msk = 8; msk; msk >>= 1)
                mx = fmaxf(mx, __shfl_xor_sync(0xffffffffu, mx, msk));
            float mnew = fmaxf(m[i], mx);
            float f = __expf(m[i] - mnew);
            float rs = 0.f;
            #pragma unroll
            for (int j = 0; j < 4; j++) {
                s[i][j] = __expf(s[i][j] - mnew);
                rs += s[i][j];
            }
            #pragma unroll
            for (int msk = 8; msk; msk >>= 1)
                rs += __shfl_xor_sync(0xffffffffu, rs, msk);
            l[i] = l[i] * f + rs;
            m[i] = mnew;
            #pragma unroll
            for (int j = 0; j < 4; j++) acc[i][j] *= f;
            *(float4*)&Ps[(ty * 4 + i) * SMP + tx * 4] =
                make_float4(s[i][0], s[i][1], s[i][2], s[i][3]);
        }
        __syncthreads();
        #pragma unroll 8
        for (int cc = 0; cc < 64; cc++) {
            float pa[4], va[4];
            pa[0] = Ps[(ty * 4 + 0) * SMP + cc];
            pa[1] = Ps[(ty * 4 + 1) * SMP + cc];
            pa[2] = Ps[(ty * 4 + 2) * SMP + cc];
            pa[3] = Ps[(ty * 4 + 3) * SMP + cc];
            *(float4*)va = *(float4*)&Vs[cc * SMP + tx * 4];
            #pragma unroll
            for (int i = 0; i < 4; i++)
                #pragma unroll
                for (int j = 0; j < 4; j++)
                    acc[i][j] += pa[i] * va[j];
        }
    }

    #pragma unroll
    for (int i = 0; i < 4; i++) {
        int qr = q0 + ty * 4 + i;
        if (qr < SEQ) {
            float invl = 1.f / l[i];
            float4 ov = make_float4(acc[i][0] * invl, acc[i][1] * invl,
                                    acc[i][2] * invl, acc[i][3] * invl);
            *(float4*)&o[(size_t)(b * SEQ + qr) * CDIM + h * 64 + tx * 4] = ov;
        }
    }
}

// ---------------- orchestration ---------------------------------------------
extern "C" void kernel_launch(void* const* d_in, const int* in_sizes, int n_in,
                              void* d_out, int out_size) {
    const float* x      = (const float*)d_in[0];
    const float* ln1_w  = (const float*)d_in[1];
    const float* ln1_b  = (const float*)d_in[2];
    const float* qkv_w  = (const float*)d_in[3];
    const float* qkv_b  = (const float*)d_in[4];
    const float* proj_w = (const float*)d_in[5];
    const float* proj_b = (const float*)d_in[6];
    const float* ln2_w  = (const float*)d_in[7];
    const float* ln2_b  = (const float*)d_in[8];
    const float* fc1_w  = (const float*)d_in[9];
    const float* fc1_b  = (const float*)d_in[10];
    const float* fc2_w  = (const float*)d_in[11];
    const float* fc2_b  = (const float*)d_in[12];
    float* out = (float*)d_out;

    float *h, *qkvb, *ob, *x1, *mid;
    cudaGetSymbolAddress((void**)&h,    g_h);
    cudaGetSymbolAddress((void**)&qkvb, g_qkv);
    cudaGetSymbolAddress((void**)&ob,   g_o);
    cudaGetSymbolAddress((void**)&x1,   g_x1);
    cudaGetSymbolAddress((void**)&mid,  g_mid);

    const int gy = (ROWS + 127) / 128;   // 145

    ln_kernel<<<ROWS, 256>>>(x, ln1_w, ln1_b, h);
    gemm_tc<0><<<dim3(3 * CDIM / 128, gy), 256>>>(h, qkv_w, qkv_b, nullptr,
                                                  qkvb, ROWS, 3 * CDIM, CDIM);
    int smem = 4 * 64 * SMP * sizeof(float);
    cudaFuncSetAttribute(attn_kernel, cudaFuncAttributeMaxDynamicSharedMemorySize, smem);
    attn_kernel<<<dim3(BATCH * NHEADS, (SEQ + 63) / 64), 256, smem>>>(qkvb, ob);
    gemm_tc<1><<<dim3(CDIM / 128, gy), 256>>>(ob, proj_w, proj_b, x,
                                              x1, ROWS, CDIM, CDIM);
    ln_kernel<<<ROWS, 256>>>(x1, ln2_w, ln2_b, h);
    gemm_tc<2><<<dim3(HDIM / 128, gy), 256>>>(h, fc1_w, fc1_b, nullptr,
                                              mid, ROWS, HDIM, CDIM);
    gemm_tc<1><<<dim3(CDIM / 128, gy), 256>>>(mid, fc2_w, fc2_b, x1,
                                              out, ROWS, CDIM, HDIM);
}

// round 7
// speedup vs baseline: 2.0915x; 1.0571x over previous
#include <cuda_runtime.h>
#include <cuda_bf16.h>
#include <math.h>

#define BATCH   32
#define SEQ     577
#define CDIM    1024
#define HDIM    4096
#define NHEADS  16
#define ROWS    (BATCH * SEQ)          // 18464

typedef __nv_bfloat16 bf16;
typedef __nv_bfloat162 bf162;

// ---------------- scratch ----------------------------------------------------
__device__ float g_qkv[(size_t)ROWS * 3 * CDIM];
__device__ float g_x1 [(size_t)ROWS * CDIM];
__device__ bf16  g_h_hi [(size_t)ROWS * CDIM],  g_h_lo [(size_t)ROWS * CDIM];
__device__ bf16  g_o_hi [(size_t)ROWS * CDIM],  g_o_lo [(size_t)ROWS * CDIM];
__device__ bf16  g_mid_hi[(size_t)ROWS * HDIM], g_mid_lo[(size_t)ROWS * HDIM];
#define NW_TOT (3*CDIM*CDIM + CDIM*CDIM + HDIM*CDIM + CDIM*HDIM)   // 12,582,912
__device__ bf16  g_w_hi[(size_t)NW_TOT], g_w_lo[(size_t)NW_TOT];

__device__ __forceinline__ void split1(float v, bf16& h, bf16& l) {
    h = __float2bfloat16(v);
    l = __float2bfloat16(v - __bfloat162float(h));
}

// ---------------- weight split (elementwise) --------------------------------
__global__ void split_kernel(const float* __restrict__ in,
                             bf16* __restrict__ oh, bf16* __restrict__ ol, int n) {
    int i = (blockIdx.x * blockDim.x + threadIdx.x) * 4;
    if (i >= n) return;
    float4 v = *(const float4*)&in[i];
    bf16 h0,l0,h1,l1,h2,l2,h3,l3;
    split1(v.x,h0,l0); split1(v.y,h1,l1); split1(v.z,h2,l2); split1(v.w,h3,l3);
    *(bf162*)&oh[i]   = bf162(h0,h1); *(bf162*)&oh[i+2] = bf162(h2,h3);
    *(bf162*)&ol[i]   = bf162(l0,l1); *(bf162*)&ol[i+2] = bf162(l2,l3);
}

// ---------------- LayerNorm -> split bf16 ------------------------------------
__global__ void ln_kernel(const float* __restrict__ x,
                          const float* __restrict__ w,
                          const float* __restrict__ b,
                          bf16* __restrict__ oh, bf16* __restrict__ ol) {
    __shared__ float red[16];
    int row = blockIdx.x;
    int t = threadIdx.x;
    const float4* xr = (const float4*)(x + (size_t)row * CDIM);
    float4 v = xr[t];
    float s  = v.x + v.y + v.z + v.w;
    float ss = v.x*v.x + v.y*v.y + v.z*v.z + v.w*v.w;
    #pragma unroll
    for (int m = 16; m; m >>= 1) {
        s  += __shfl_xor_sync(0xffffffffu, s,  m);
        ss += __shfl_xor_sync(0xffffffffu, ss, m);
    }
    int warp = t >> 5;
    if ((t & 31) == 0) { red[warp] = s; red[warp + 8] = ss; }
    __syncthreads();
    s = 0.f; ss = 0.f;
    #pragma unroll
    for (int i = 0; i < 8; i++) { s += red[i]; ss += red[i + 8]; }
    float mean = s * (1.0f / CDIM);
    float var  = ss * (1.0f / CDIM) - mean * mean;
    float inv  = rsqrtf(var + 1e-6f);
    float4 wv = ((const float4*)w)[t];
    float4 bv = ((const float4*)b)[t];
    float o0 = (v.x - mean) * inv * wv.x + bv.x;
    float o1 = (v.y - mean) * inv * wv.y + bv.y;
    float o2 = (v.z - mean) * inv * wv.z + bv.z;
    float o3 = (v.w - mean) * inv * wv.w + bv.w;
    bf16 h0,l0,h1,l1,h2,l2,h3,l3;
    split1(o0,h0,l0); split1(o1,h1,l1); split1(o2,h2,l2); split1(o3,h3,l3);
    size_t off = (size_t)row * CDIM + t * 4;
    *(bf162*)&oh[off]   = bf162(h0,h1); *(bf162*)&oh[off+2] = bf162(h2,h3);
    *(bf162*)&ol[off]   = bf162(l0,l1); *(bf162*)&ol[off+2] = bf162(l2,l3);
}

// ---------------- tensor-core GEMM -------------------------------------------
__device__ __forceinline__ unsigned smem_u32(const void* p) {
    return (unsigned)__cvta_generic_to_shared(p);
}
__device__ __forceinline__ void cp16(void* dst, const void* src) {
    asm volatile("cp.async.cg.shared.global [%0], [%1], 16;\n"
                 :: "r"(smem_u32(dst)), "l"(src));
}
__device__ __forceinline__ void ldm_x4(unsigned* r, unsigned addr) {
    asm volatile("ldmatrix.sync.aligned.m8n8.x4.shared.b16 {%0,%1,%2,%3}, [%4];\n"
                 : "=r"(r[0]), "=r"(r[1]), "=r"(r[2]), "=r"(r[3]) : "r"(addr));
}
__device__ __forceinline__ void mma16816(float* c, const unsigned* a, const unsigned* b) {
    asm volatile("mma.sync.aligned.m16n8k16.row.col.f32.bf16.bf16.f32 "
                 "{%0,%1,%2,%3},{%4,%5,%6,%7},{%8,%9},{%0,%1,%2,%3};\n"
                 : "+f"(c[0]), "+f"(c[1]), "+f"(c[2]), "+f"(c[3])
                 : "r"(a[0]), "r"(a[1]), "r"(a[2]), "r"(a[3]), "r"(b[0]), "r"(b[1]));
}

#define SPAD 40          // 32 data + 8 pad bf16 -> 80B row stride (16B-aligned)
#define TILE_ELE (128 * SPAD)
// smem layout: 8 tiles of 128xSPAD bf16: [st*2+p] for A (0..3), 4+[st*2+p] for B
#define SMEM_BYTES (8 * TILE_ELE * sizeof(bf16))   // 81,920

// C = A*B^T + epilogue. EPI: 0=+bias->f32, 1=+bias+res->f32, 2=+bias+GELU->bf16 split
template<int EPI>
__global__ __launch_bounds__(256)
void gemm_tc(const bf16* __restrict__ Ah, const bf16* __restrict__ Al,
             const bf16* __restrict__ Bh, const bf16* __restrict__ Bl,
             const float* __restrict__ bias, const float* __restrict__ res,
             float* __restrict__ C, bf16* __restrict__ Chi, bf16* __restrict__ Clo,
             int M, int N, int K) {
    extern __shared__ bf16 smem[];
    int tid  = threadIdx.x;
    int lane = tid & 31;
    int warp = tid >> 5;
    int wm = warp >> 2;
    int wn = warp & 3;
    int bm = blockIdx.y * 128;
    int bn = blockIdx.x * 128;

    float c[4][4][4];
    #pragma unroll
    for (int i = 0; i < 4; i++)
        #pragma unroll
        for (int j = 0; j < 4; j++)
            #pragma unroll
            for (int r = 0; r < 4; r++) c[i][j][r] = 0.f;

    const bf16* srcs[4] = {Ah, Al, Bh, Bl};

    // issue cp.async for tile t into stage st: 2048 16B chunks, 8 per thread
    auto issue = [&](int t, int st) {
        int k0 = t * 32;
        #pragma unroll
        for (int l = 0; l < 8; l++) {
            int arr = l >> 1;                      // 0=Ah 1=Al 2=Bh 3=Bl
            int local = tid + ((l & 1) << 8);      // 0..511
            int r = local >> 2;
            int ch = local & 3;
            int gr = (arr < 2) ? min(bm + r, M - 1) : (bn + r);
            const bf16* src = srcs[arr] + (size_t)gr * K + k0 + ch * 8;
            bf16* dst = smem + ((arr < 2 ? arr : 2 + arr) + (st << 1)) * TILE_ELE
                             + r * SPAD + ch * 8;
            cp16(dst, src);
        }
        asm volatile("cp.async.commit_group;\n");
    };

    int nT = K >> 5;
    issue(0, 0);

    for (int t = 0; t < nT; t++) {
        int st = t & 1;
        asm volatile("cp.async.wait_group 0;\n");
        __syncthreads();
        if (t + 1 < nT) issue(t + 1, st ^ 1);

        const bf16* As0 = smem + ((st << 1) + 0) * TILE_ELE;   // A hi
        const bf16* As1 = smem + ((st << 1) + 1) * TILE_ELE;   // A lo
        const bf16* Bs0 = smem + (4 + (st << 1) + 0) * TILE_ELE;
        const bf16* Bs1 = smem + (4 + (st << 1) + 1) * TILE_ELE;

        #pragma unroll
        for (int kk = 0; kk < 2; kk++) {
            int ki = kk << 4;
            unsigned ah[4][4], al[4][4];
            #pragma unroll
            for (int i = 0; i < 4; i++) {
                int arow = wm * 64 + i * 16 + (lane & 15);
                int acol = ki + ((lane >> 4) << 3);
                ldm_x4(ah[i], smem_u32(As0 + arow * SPAD + acol));
                ldm_x4(al[i], smem_u32(As1 + arow * SPAD + acol));
            }
            unsigned bh[4][2], bl[4][2];
            #pragma unroll
            for (int jp = 0; jp < 2; jp++) {
                int brow = wn * 32 + jp * 16 + (((lane >> 4) & 1) << 3) + (lane & 7);
                int bcol = ki + (((lane >> 3) & 1) << 3);
                unsigned t4[4];
                ldm_x4(t4, smem_u32(Bs0 + brow * SPAD + bcol));
                bh[2*jp][0] = t4[0]; bh[2*jp][1] = t4[1];
                bh[2*jp+1][0] = t4[2]; bh[2*jp+1][1] = t4[3];
                ldm_x4(t4, smem_u32(Bs1 + brow * SPAD + bcol));
                bl[2*jp][0] = t4[0]; bl[2*jp][1] = t4[1];
                bl[2*jp+1][0] = t4[2]; bl[2*jp+1][1] = t4[3];
            }
            #pragma unroll
            for (int i = 0; i < 4; i++)
                #pragma unroll
                for (int j = 0; j < 4; j++) {
                    mma16816(c[i][j], ah[i], bh[j]);
                    mma16816(c[i][j], ah[i], bl[j]);
                    mma16816(c[i][j], al[i], bh[j]);
                }
        }
        __syncthreads();
    }

    // epilogue
    int g = lane >> 2, t2 = (lane & 3) << 1;
    #pragma unroll
    for (int i = 0; i < 4; i++) {
        #pragma unroll
        for (int j = 0; j < 4; j++) {
            int cc = bn + wn * 32 + j * 8 + t2;
            float2 bv = *(const float2*)&bias[cc];
            #pragma unroll
            for (int half = 0; half < 2; half++) {
                int gr = bm + wm * 64 + i * 16 + g + half * 8;
                if (gr < M) {
                    float vx = c[i][j][half * 2 + 0] + bv.x;
                    float vy = c[i][j][half * 2 + 1] + bv.y;
                    size_t off = (size_t)gr * N + cc;
                    if (EPI == 1) {
                        float2 rv = *(const float2*)&res[off];
                        vx += rv.x; vy += rv.y;
                    }
                    if (EPI == 2) {
                        vx = 0.5f * vx * (1.f + erff(vx * 0.70710678118654752f));
                        vy = 0.5f * vy * (1.f + erff(vy * 0.70710678118654752f));
                        bf16 hx, lx, hy, ly;
                        split1(vx, hx, lx); split1(vy, hy, ly);
                        *(bf162*)&Chi[off] = bf162(hx, hy);
                        *(bf162*)&Clo[off] = bf162(lx, ly);
                    } else {
                        *(float2*)&C[off] = make_float2(vx, vy);
                    }
                }
            }
        }
    }
}

// ---------------- fused attention (flash-style, fp32 SIMT) ------------------
#define SMP 68
__global__ __launch_bounds__(256)
void attn_kernel(const float* __restrict__ qkv,
                 bf16* __restrict__ ohp, bf16* __restrict__ olp) {
    extern __shared__ float sm[];
    float* QsT = sm;
    float* KsT = sm + 64 * SMP;
    float* Vs  = sm + 2 * 64 * SMP;
    float* Ps  = sm + 3 * 64 * SMP;

    int bh = blockIdx.x;
    int b = bh >> 4, h = bh & 15;
    int q0 = blockIdx.y * 64;
    int tid = threadIdx.x;
    int tx = tid & 15, ty = tid >> 4;

    for (int i = tid; i < 1024; i += 256) {
        int r = i >> 4, d4 = (i & 15) * 4;
        int qr = q0 + r;
        float4 v = make_float4(0.f, 0.f, 0.f, 0.f);
        if (qr < SEQ)
            v = *(const float4*)&qkv[(size_t)(b * SEQ + qr) * 3072 + h * 64 + d4];
        QsT[(d4 + 0) * SMP + r] = v.x * 0.125f;
        QsT[(d4 + 1) * SMP + r] = v.y * 0.125f;
        QsT[(d4 + 2) * SMP + r] = v.z * 0.125f;
        QsT[(d4 + 3) * SMP + r] = v.w * 0.125f;
    }

    float m[4], l[4], acc[4][4];
    #pragma unroll
    for (int i = 0; i < 4; i++) {
        m[i] = -1e30f; l[i] = 0.f;
        #pragma unroll
        for (int j = 0; j < 4; j++) acc[i][j] = 0.f;
    }

    for (int kt = 0; kt < 10; kt++) {
        int k0 = kt * 64;
        __syncthreads();
        for (int i = tid; i < 1024; i += 256) {
            int cc = i >> 4, d4 = (i & 15) * 4;
            int kr = k0 + cc;
            float4 kv = make_float4(0.f, 0.f, 0.f, 0.f);
            float4 vv = make_float4(0.f, 0.f, 0.f, 0.f);
            if (kr < SEQ) {
                size_t base = (size_t)(b * SEQ + kr) * 3072 + h * 64 + d4;
                kv = *(const float4*)&qkv[base + 1024];
                vv = *(const float4*)&qkv[base + 2048];
            }
            KsT[(d4 + 0) * SMP + cc] = kv.x;
            KsT[(d4 + 1) * SMP + cc] = kv.y;
            KsT[(d4 + 2) * SMP + cc] = kv.z;
            KsT[(d4 + 3) * SMP + cc] = kv.w;
            *(float4*)&Vs[cc * SMP + d4] = vv;
        }
        __syncthreads();

        float s[4][4];
        #pragma unroll
        for (int i = 0; i < 4; i++)
            #pragma unroll
            for (int j = 0; j < 4; j++) s[i][j] = 0.f;
        #pragma unroll 8
        for (int d = 0; d < 64; d++) {
            float qa[4], ka[4];
            *(float4*)qa = *(float4*)&QsT[d * SMP + ty * 4];
            *(float4*)ka = *(float4*)&KsT[d * SMP + tx * 4];
            #pragma unroll
            for (int i = 0; i < 4; i++)
                #pragma unroll
                for (int j = 0; j < 4; j++)
                    s[i][j] += qa[i] * ka[j];
        }
        #pragma unroll
        for (int j = 0; j < 4; j++)
            if (k0 + tx * 4 + j >= SEQ) {
                #pragma unroll
                for (int i = 0; i < 4; i++) s[i][j] = -1e30f;
            }
        #pragma unroll
        for (int i = 0; i < 4; i++) {
            float mx = fmaxf(fmaxf(s[i][0], s[i][1]), fmaxf(s[i][2], s[i][3]));
            #pragma unroll
            for (int msk = 8; msk; msk >>= 1)
                mx = fmaxf(mx, __shfl_xor_sync(0xffffffffu, mx, msk));
            float mnew = fmaxf(m[i], mx);
            float f = __expf(m[i] - mnew);
            float rs = 0.f;
            #pragma unroll
            for (int j = 0; j < 4; j++) {
                s[i][j] = __expf(s[i][j] - mnew);
                rs += s[i][j];
            }
            #pragma unroll
            for (int msk = 8; msk; msk >>= 1)
                rs += __shfl_xor_sync(0xffffffffu, rs, msk);
            l[i] = l[i] * f + rs;
            m[i] = mnew;
            #pragma unroll
            for (int j = 0; j < 4; j++) acc[i][j] *= f;
            *(float4*)&Ps[(ty * 4 + i) * SMP + tx * 4] =
                make_float4(s[i][0], s[i][1], s[i][2], s[i][3]);
        }
        __syncthreads();
        #pragma unroll 8
        for (int cc = 0; cc < 64; cc++) {
            float pa[4], va[4];
            pa[0] = Ps[(ty * 4 + 0) * SMP + cc];
            pa[1] = Ps[(ty * 4 + 1) * SMP + cc];
            pa[2] = Ps[(ty * 4 + 2) * SMP + cc];
            pa[3] = Ps[(ty * 4 + 3) * SMP + cc];
            *(float4*)va = *(float4*)&Vs[cc * SMP + tx * 4];
            #pragma unroll
            for (int i = 0; i < 4; i++)
                #pragma unroll
                for (int j = 0; j < 4; j++)
                    acc[i][j] += pa[i] * va[j];
        }
    }

    #pragma unroll
    for (int i = 0; i < 4; i++) {
        int qr = q0 + ty * 4 + i;
        if (qr < SEQ) {
            float invl = 1.f / l[i];
            float v0 = acc[i][0] * invl, v1 = acc[i][1] * invl;
            float v2 = acc[i][2] * invl, v3 = acc[i][3] * invl;
            bf16 h0,l0,h1,l1,h2,l2,h3,l3;
            split1(v0,h0,l0); split1(v1,h1,l1); split1(v2,h2,l2); split1(v3,h3,l3);
            size_t off = (size_t)(b * SEQ + qr) * CDIM + h * 64 + tx * 4;
            *(bf162*)&ohp[off]   = bf162(h0,h1); *(bf162*)&ohp[off+2] = bf162(h2,h3);
            *(bf162*)&olp[off]   = bf162(l0,l1); *(bf162*)&olp[off+2] = bf162(l2,l3);
        }
    }
}

// ---------------- orchestration ---------------------------------------------
extern "C" void kernel_launch(void* const* d_in, const int* in_sizes, int n_in,
                              void* d_out, int out_size) {
    const float* x      = (const float*)d_in[0];
    const float* ln1_w  = (const float*)d_in[1];
    const float* ln1_b  = (const float*)d_in[2];
    const float* qkv_w  = (const float*)d_in[3];
    const float* qkv_b  = (const float*)d_in[4];
    const float* proj_w = (const float*)d_in[5];
    const float* proj_b = (const float*)d_in[6];
    const float* ln2_w  = (const float*)d_in[7];
    const float* ln2_b  = (const float*)d_in[8];
    const float* fc1_w  = (const float*)d_in[9];
    const float* fc1_b  = (const float*)d_in[10];
    const float* fc2_w  = (const float*)d_in[11];
    const float* fc2_b  = (const float*)d_in[12];
    float* out = (float*)d_out;

    float *qkvf, *x1;
    bf16 *hh, *hl, *oh, *ol, *mh, *ml, *wh, *wl;
    cudaGetSymbolAddress((void**)&qkvf, g_qkv);
    cudaGetSymbolAddress((void**)&x1,   g_x1);
    cudaGetSymbolAddress((void**)&hh,   g_h_hi);
    cudaGetSymbolAddress((void**)&hl,   g_h_lo);
    cudaGetSymbolAddress((void**)&oh,   g_o_hi);
    cudaGetSymbolAddress((void**)&ol,   g_o_lo);
    cudaGetSymbolAddress((void**)&mh,   g_mid_hi);
    cudaGetSymbolAddress((void**)&ml,   g_mid_lo);
    cudaGetSymbolAddress((void**)&wh,   g_w_hi);
    cudaGetSymbolAddress((void**)&wl,   g_w_lo);

    // weight offsets in the combined buffer
    const size_t OFF_QKV  = 0;
    const size_t OFF_PROJ = (size_t)3 * CDIM * CDIM;
    const size_t OFF_FC1  = OFF_PROJ + (size_t)CDIM * CDIM;
    const size_t OFF_FC2  = OFF_FC1 + (size_t)HDIM * CDIM;

    cudaFuncSetAttribute(gemm_tc<0>, cudaFuncAttributeMaxDynamicSharedMemorySize, SMEM_BYTES);
    cudaFuncSetAttribute(gemm_tc<1>, cudaFuncAttributeMaxDynamicSharedMemorySize, SMEM_BYTES);
    cudaFuncSetAttribute(gemm_tc<2>, cudaFuncAttributeMaxDynamicSharedMemorySize, SMEM_BYTES);

    // pre-split weights (cheap, once per replay)
    split_kernel<<<(3*CDIM*CDIM)/1024, 256>>>(qkv_w,  wh+OFF_QKV,  wl+OFF_QKV,  3*CDIM*CDIM);
    split_kernel<<<(CDIM*CDIM)/1024,   256>>>(proj_w, wh+OFF_PROJ, wl+OFF_PROJ, CDIM*CDIM);
    split_kernel<<<(HDIM*CDIM)/1024,   256>>>(fc1_w,  wh+OFF_FC1,  wl+OFF_FC1,  HDIM*CDIM);
    split_kernel<<<(CDIM*HDIM)/1024,   256>>>(fc2_w,  wh+OFF_FC2,  wl+OFF_FC2,  CDIM*HDIM);

    const int gy = (ROWS + 127) / 128;   // 145

    // LN1 -> split h
    ln_kernel<<<ROWS, 256>>>(x, ln1_w, ln1_b, hh, hl);
    // QKV
    gemm_tc<0><<<dim3(3*CDIM/128, gy), 256, SMEM_BYTES>>>(
        hh, hl, wh+OFF_QKV, wl+OFF_QKV, qkv_b, nullptr,
        qkvf, nullptr, nullptr, ROWS, 3*CDIM, CDIM);
    // attention -> split o
    int smem = 4 * 64 * SMP * sizeof(float);
    cudaFuncSetAttribute(attn_kernel, cudaFuncAttributeMaxDynamicSharedMemorySize, smem);
    attn_kernel<<<dim3(BATCH * NHEADS, (SEQ + 63) / 64), 256, smem>>>(qkvf, oh, ol);
    // proj + residual(x) -> x1 (fp32)
    gemm_tc<1><<<dim3(CDIM/128, gy), 256, SMEM_BYTES>>>(
        oh, ol, wh+OFF_PROJ, wl+OFF_PROJ, proj_b, x,
        x1, nullptr, nullptr, ROWS, CDIM, CDIM);
    // LN2 -> split h
    ln_kernel<<<ROWS, 256>>>(x1, ln2_w, ln2_b, hh, hl);
    // fc1 + GELU -> split mid
    gemm_tc<2><<<dim3(HDIM/128, gy), 256, SMEM_BYTES>>>(
        hh, hl, wh+OFF_FC1, wl+OFF_FC1, fc1_b, nullptr,
        nullptr, mh, ml, ROWS, HDIM, CDIM);
    // fc2 + residual(x1) -> out
    gemm_tc<1><<<dim3(CDIM/128, gy), 256, SMEM_BYTES>>>(
        mh, ml, wh+OFF_FC2, wl+OFF_FC2, fc2_b, x1,
        out, nullptr, nullptr, ROWS, CDIM, HDIM);
}

// round 10
// speedup vs baseline: 2.2091x; 1.0562x over previous
#include <cuda_runtime.h>
#include <cuda_bf16.h>
#include <math.h>
#include <stdint.h>

#define BATCH   32
#define SEQ     577
#define CDIM    1024
#define HDIM    4096
#define NHEADS  16
#define ROWS    (BATCH * SEQ)          // 18464

typedef __nv_bfloat16 bf16;
typedef __nv_bfloat162 bf162;

// ---------------- scratch ----------------------------------------------------
__device__ float g_qkv[(size_t)ROWS * 3 * CDIM];
__device__ float g_x1 [(size_t)ROWS * CDIM];
__device__ bf16  g_h_hi [(size_t)ROWS * CDIM],  g_h_lo [(size_t)ROWS * CDIM];
__device__ bf16  g_o_hi [(size_t)ROWS * CDIM],  g_o_lo [(size_t)ROWS * CDIM];
__device__ bf16  g_mid_hi[(size_t)ROWS * HDIM], g_mid_lo[(size_t)ROWS * HDIM];
#define NW_TOT (3*CDIM*CDIM + CDIM*CDIM + HDIM*CDIM + CDIM*HDIM)
__device__ bf16  g_w_hi[(size_t)NW_TOT], g_w_lo[(size_t)NW_TOT];

__device__ __forceinline__ void split1(float v, bf16& h, bf16& l) {
    h = __float2bfloat16(v);
    l = __float2bfloat16(v - __bfloat162float(h));
}

// ---------------- weight split ------------------------------------------------
__global__ void split_kernel(const float* __restrict__ in,
                             bf16* __restrict__ oh, bf16* __restrict__ ol, int n) {
    int i = (blockIdx.x * blockDim.x + threadIdx.x) * 4;
    if (i >= n) return;
    float4 v = *(const float4*)&in[i];
    bf16 h0,l0,h1,l1,h2,l2,h3,l3;
    split1(v.x,h0,l0); split1(v.y,h1,l1); split1(v.z,h2,l2); split1(v.w,h3,l3);
    *(bf162*)&oh[i]   = bf162(h0,h1); *(bf162*)&oh[i+2] = bf162(h2,h3);
    *(bf162*)&ol[i]   = bf162(l0,l1); *(bf162*)&ol[i+2] = bf162(l2,l3);
}

// ---------------- LayerNorm -> split bf16 ------------------------------------
__global__ void ln_kernel(const float* __restrict__ x,
                          const float* __restrict__ w,
                          const float* __restrict__ b,
                          bf16* __restrict__ oh, bf16* __restrict__ ol) {
    __shared__ float red[16];
    int row = blockIdx.x;
    int t = threadIdx.x;
    const float4* xr = (const float4*)(x + (size_t)row * CDIM);
    float4 v = xr[t];
    float s  = v.x + v.y + v.z + v.w;
    float ss = v.x*v.x + v.y*v.y + v.z*v.z + v.w*v.w;
    #pragma unroll
    for (int m = 16; m; m >>= 1) {
        s  += __shfl_xor_sync(0xffffffffu, s,  m);
        ss += __shfl_xor_sync(0xffffffffu, ss, m);
    }
    int warp = t >> 5;
    if ((t & 31) == 0) { red[warp] = s; red[warp + 8] = ss; }
    __syncthreads();
    s = 0.f; ss = 0.f;
    #pragma unroll
    for (int i = 0; i < 8; i++) { s += red[i]; ss += red[i + 8]; }
    float mean = s * (1.0f / CDIM);
    float var  = ss * (1.0f / CDIM) - mean * mean;
    float inv  = rsqrtf(var + 1e-6f);
    float4 wv = ((const float4*)w)[t];
    float4 bv = ((const float4*)b)[t];
    float o0 = (v.x - mean) * inv * wv.x + bv.x;
    float o1 = (v.y - mean) * inv * wv.y + bv.y;
    float o2 = (v.z - mean) * inv * wv.z + bv.z;
    float o3 = (v.w - mean) * inv * wv.w + bv.w;
    bf16 h0,l0,h1,l1,h2,l2,h3,l3;
    split1(o0,h0,l0); split1(o1,h1,l1); split1(o2,h2,l2); split1(o3,h3,l3);
    size_t off = (size_t)row * CDIM + t * 4;
    *(bf162*)&oh[off]   = bf162(h0,h1); *(bf162*)&oh[off+2] = bf162(h2,h3);
    *(bf162*)&ol[off]   = bf162(l0,l1); *(bf162*)&ol[off+2] = bf162(l2,l3);
}

// ---------------- tensor-core GEMM (mma.sync, 2 CTA/SM) ----------------------
__device__ __forceinline__ unsigned smem_u32(const void* p) {
    return (unsigned)__cvta_generic_to_shared(p);
}
__device__ __forceinline__ void cp16(void* dst, const void* src) {
    asm volatile("cp.async.cg.shared.global [%0], [%1], 16;\n"
                 :: "r"(smem_u32(dst)), "l"(src));
}
__device__ __forceinline__ void ldm_x4(unsigned* r, unsigned addr) {
    asm volatile("ldmatrix.sync.aligned.m8n8.x4.shared.b16 {%0,%1,%2,%3}, [%4];\n"
                 : "=r"(r[0]), "=r"(r[1]), "=r"(r[2]), "=r"(r[3]) : "r"(addr));
}
__device__ __forceinline__ void mma16816(float* c, const unsigned* a, const unsigned* b) {
    asm volatile("mma.sync.aligned.m16n8k16.row.col.f32.bf16.bf16.f32 "
                 "{%0,%1,%2,%3},{%4,%5,%6,%7},{%8,%9},{%0,%1,%2,%3};\n"
                 : "+f"(c[0]), "+f"(c[1]), "+f"(c[2]), "+f"(c[3])
                 : "r"(a[0]), "r"(a[1]), "r"(a[2]), "r"(a[3]), "r"(b[0]), "r"(b[1]));
}

#define SPAD 40          // 32 data + 8 pad bf16 -> 80B row stride
#define TILE_ELE (128 * SPAD)
#define SMEM_BYTES (8 * TILE_ELE * sizeof(bf16))   // 81,920 per CTA; 2 CTAs/SM OK

// C = A*B^T + epilogue. EPI: 0=+bias->f32, 1=+bias+res->f32, 2=+bias+GELU->bf16 split
template<int EPI>
__global__ __launch_bounds__(256, 2)
void gemm_tc(const bf16* __restrict__ Ah, const bf16* __restrict__ Al,
             const bf16* __restrict__ Bh, const bf16* __restrict__ Bl,
             const float* __restrict__ bias, const float* __restrict__ res,
             float* __restrict__ C, bf16* __restrict__ Chi, bf16* __restrict__ Clo,
             int M, int N, int K) {
    extern __shared__ bf16 smem[];
    int tid  = threadIdx.x;
    int lane = tid & 31;
    int warp = tid >> 5;
    int wm = warp >> 2;
    int wn = warp & 3;
    int bm = blockIdx.y * 128;
    int bn = blockIdx.x * 128;

    float c[4][4][4];
    #pragma unroll
    for (int i = 0; i < 4; i++)
        #pragma unroll
        for (int j = 0; j < 4; j++)
            #pragma unroll
            for (int r = 0; r < 4; r++) c[i][j][r] = 0.f;

    const bf16* srcs[4] = {Ah, Al, Bh, Bl};

    auto issue = [&](int t, int st) {
        int k0 = t * 32;
        #pragma unroll
        for (int l = 0; l < 8; l++) {
            int arr = l >> 1;                      // 0=Ah 1=Al 2=Bh 3=Bl
            int local = tid + ((l & 1) << 8);      // 0..511
            int r = local >> 2;
            int ch = local & 3;
            int gr = (arr < 2) ? min(bm + r, M - 1) : (bn + r);
            const bf16* src = srcs[arr] + (size_t)gr * K + k0 + ch * 8;
            bf16* dst = smem + ((arr < 2 ? arr : 2 + arr) + (st << 1)) * TILE_ELE
                             + r * SPAD + ch * 8;
            cp16(dst, src);
        }
        asm volatile("cp.async.commit_group;\n");
    };

    int nT = K >> 5;
    issue(0, 0);

    for (int t = 0; t < nT; t++) {
        int st = t & 1;
        asm volatile("cp.async.wait_group 0;\n");
        __syncthreads();
        if (t + 1 < nT) issue(t + 1, st ^ 1);

        const bf16* As0 = smem + ((st << 1) + 0) * TILE_ELE;
        const bf16* As1 = smem + ((st << 1) + 1) * TILE_ELE;
        const bf16* Bs0 = smem + (4 + (st << 1) + 0) * TILE_ELE;
        const bf16* Bs1 = smem + (4 + (st << 1) + 1) * TILE_ELE;

        #pragma unroll
        for (int kk = 0; kk < 2; kk++) {
            int ki = kk << 4;
            // B fragments for this k-step (hoisted)
            unsigned bh[4][2], bl[4][2];
            #pragma unroll
            for (int jp = 0; jp < 2; jp++) {
                int brow = wn * 32 + jp * 16 + (((lane >> 4) & 1) << 3) + (lane & 7);
                int bcol = ki + (((lane >> 3) & 1) << 3);
                unsigned t4[4];
                ldm_x4(t4, smem_u32(Bs0 + brow * SPAD + bcol));
                bh[2*jp][0] = t4[0]; bh[2*jp][1] = t4[1];
                bh[2*jp+1][0] = t4[2]; bh[2*jp+1][1] = t4[3];
                ldm_x4(t4, smem_u32(Bs1 + brow * SPAD + bcol));
                bl[2*jp][0] = t4[0]; bl[2*jp][1] = t4[1];
                bl[2*jp+1][0] = t4[2]; bl[2*jp+1][1] = t4[3];
            }
            // A fragments loaded per-i: only 8 live frag regs, LDSM of i+1
            // overlaps MMAs of i
            #pragma unroll
            for (int i = 0; i < 4; i++) {
                int arow = wm * 64 + i * 16 + (lane & 15);
                int acol = ki + ((lane >> 4) << 3);
                unsigned ah[4], al[4];
                ldm_x4(ah, smem_u32(As0 + arow * SPAD + acol));
                ldm_x4(al, smem_u32(As1 + arow * SPAD + acol));
                #pragma unroll
                for (int j = 0; j < 4; j++) {
                    mma16816(c[i][j], ah, bh[j]);
                    mma16816(c[i][j], ah, bl[j]);
                    mma16816(c[i][j], al, bh[j]);
                }
            }
        }
        __syncthreads();
    }

    // epilogue
    int g = lane >> 2, t2 = (lane & 3) << 1;
    #pragma unroll
    for (int i = 0; i < 4; i++) {
        #pragma unroll
        for (int j = 0; j < 4; j++) {
            int cc = bn + wn * 32 + j * 8 + t2;
            float2 bv = *(const float2*)&bias[cc];
            #pragma unroll
            for (int half = 0; half < 2; half++) {
                int gr = bm + wm * 64 + i * 16 + g + half * 8;
                if (gr < M) {
                    float vx = c[i][j][half * 2 + 0] + bv.x;
                    float vy = c[i][j][half * 2 + 1] + bv.y;
                    size_t off = (size_t)gr * N + cc;
                    if (EPI == 1) {
                        float2 rv = *(const float2*)&res[off];
                        vx += rv.x; vy += rv.y;
                    }
                    if (EPI == 2) {
                        vx = 0.5f * vx * (1.f + erff(vx * 0.70710678118654752f));
                        vy = 0.5f * vy * (1.f + erff(vy * 0.70710678118654752f));
                        bf16 hx, lx, hy, ly;
                        split1(vx, hx, lx); split1(vy, hy, ly);
                        *(bf162*)&Chi[off] = bf162(hx, hy);
                        *(bf162*)&Clo[off] = bf162(lx, ly);
                    } else {
                        *(float2*)&C[off] = make_float2(vx, vy);
                    }
                }
            }
        }
    }
}

// ---------------- fused attention (flash-style, fp32 SIMT) ------------------
#define SMP 68
__global__ __launch_bounds__(256)
void attn_kernel(const float* __restrict__ qkv,
                 bf16* __restrict__ ohp, bf16* __restrict__ olp) {
    extern __shared__ float sm[];
    float* QsT = sm;
    float* KsT = sm + 64 * SMP;
    float* Vs  = sm + 2 * 64 * SMP;
    float* Ps  = sm + 3 * 64 * SMP;

    int bh = blockIdx.x;
    int b = bh >> 4, h = bh & 15;
    int q0 = blockIdx.y * 64;
    int tid = threadIdx.x;
    int tx = tid & 15, ty = tid >> 4;

    for (int i = tid; i < 1024; i += 256) {
        int r = i >> 4, d4 = (i & 15) * 4;
        int qr = q0 + r;
        float4 v = make_float4(0.f, 0.f, 0.f, 0.f);
        if (qr < SEQ)
            v = *(const float4*)&qkv[(size_t)(b * SEQ + qr) * 3072 + h * 64 + d4];
        QsT[(d4 + 0) * SMP + r] = v.x * 0.125f;
        QsT[(d4 + 1) * SMP + r] = v.y * 0.125f;
        QsT[(d4 + 2) * SMP + r] = v.z * 0.125f;
        QsT[(d4 + 3) * SMP + r] = v.w * 0.125f;
    }

    float m[4], l[4], acc[4][4];
    #pragma unroll
    for (int i = 0; i < 4; i++) {
        m[i] = -1e30f; l[i] = 0.f;
        #pragma unroll
        for (int j = 0; j < 4; j++) acc[i][j] = 0.f;
    }

    for (int kt = 0; kt < 10; kt++) {
        int k0 = kt * 64;
        __syncthreads();
        for (int i = tid; i < 1024; i += 256) {
            int cc = i >> 4, d4 = (i & 15) * 4;
            int kr = k0 + cc;
            float4 kv = make_float4(0.f, 0.f, 0.f, 0.f);
            float4 vv = make_float4(0.f, 0.f, 0.f, 0.f);
            if (kr < SEQ) {
                size_t base = (size_t)(b * SEQ + kr) * 3072 + h * 64 + d4;
                kv = *(const float4*)&qkv[base + 1024];
                vv = *(const float4*)&qkv[base + 2048];
            }
            KsT[(d4 + 0) * SMP + cc] = kv.x;
            KsT[(d4 + 1) * SMP + cc] = kv.y;
            KsT[(d4 + 2) * SMP + cc] = kv.z;
            KsT[(d4 + 3) * SMP + cc] = kv.w;
            *(float4*)&Vs[cc * SMP + d4] = vv;
        }
        __syncthreads();

        float s[4][4];
        #pragma unroll
        for (int i = 0; i < 4; i++)
            #pragma unroll
            for (int j = 0; j < 4; j++) s[i][j] = 0.f;
        #pragma unroll 8
        for (int d = 0; d < 64; d++) {
            float qa[4], ka[4];
            *(float4*)qa = *(float4*)&QsT[d * SMP + ty * 4];
            *(float4*)ka = *(float4*)&KsT[d * SMP + tx * 4];
            #pragma unroll
            for (int i = 0; i < 4; i++)
                #pragma unroll
                for (int j = 0; j < 4; j++)
                    s[i][j] += qa[i] * ka[j];
        }
        #pragma unroll
        for (int j = 0; j < 4; j++)
            if (k0 + tx * 4 + j >= SEQ) {
                #pragma unroll
                for (int i = 0; i < 4; i++) s[i][j] = -1e30f;
            }
        #pragma unroll
        for (int i = 0; i < 4; i++) {
            float mx = fmaxf(fmaxf(s[i][0], s[i][1]), fmaxf(s[i][2], s[i][3]));
            #pragma unroll
            for (int msk = 8; msk; msk >>= 1)
                mx = fmaxf(mx, __shfl_xor_sync(0xffffffffu, mx, msk));
            float mnew = fmaxf(m[i], mx);
            float f = __expf(m[i] - mnew);
            float rs = 0.f;
            #pragma unroll
            for (int j = 0; j < 4; j++) {
                s[i][j] = __expf(s[i][j] - mnew);
                rs += s[i][j];
            }
            #pragma unroll
            for (int msk = 8; msk; msk >>= 1)
                rs += __shfl_xor_sync(0xffffffffu, rs, msk);
            l[i] = l[i] * f + rs;
            m[i] = mnew;
            #pragma unroll
            for (int j = 0; j < 4; j++) acc[i][j] *= f;
            *(float4*)&Ps[(ty * 4 + i) * SMP + tx * 4] =
                make_float4(s[i][0], s[i][1], s[i][2], s[i][3]);
        }
        __syncthreads();
        #pragma unroll 8
        for (int cc = 0; cc < 64; cc++) {
            float pa[4], va[4];
            pa[0] = Ps[(ty * 4 + 0) * SMP + cc];
            pa[1] = Ps[(ty * 4 + 1) * SMP + cc];
            pa[2] = Ps[(ty * 4 + 2) * SMP + cc];
            pa[3] = Ps[(ty * 4 + 3) * SMP + cc];
            *(float4*)va = *(float4*)&Vs[cc * SMP + tx * 4];
            #pragma unroll
            for (int i = 0; i < 4; i++)
                #pragma unroll
                for (int j = 0; j < 4; j++)
                    acc[i][j] += pa[i] * va[j];
        }
    }

    #pragma unroll
    for (int i = 0; i < 4; i++) {
        int qr = q0 + ty * 4 + i;
        if (qr < SEQ) {
            float invl = 1.f / l[i];
            float v0 = acc[i][0] * invl, v1 = acc[i][1] * invl;
            float v2 = acc[i][2] * invl, v3 = acc[i][3] * invl;
            bf16 h0,l0,h1,l1,h2,l2,h3,l3;
            split1(v0,h0,l0); split1(v1,h1,l1); split1(v2,h2,l2); split1(v3,h3,l3);
            size_t off = (size_t)(b * SEQ + qr) * CDIM + h * 64 + tx * 4;
            *(bf162*)&ohp[off]   = bf162(h0,h1); *(bf162*)&ohp[off+2] = bf162(h2,h3);
            *(bf162*)&olp[off]   = bf162(l0,l1); *(bf162*)&olp[off+2] = bf162(l2,l3);
        }
    }
}

// ---------------- orchestration ---------------------------------------------
extern "C" void kernel_launch(void* const* d_in, const int* in_sizes, int n_in,
                              void* d_out, int out_size) {
    const float* x      = (const float*)d_in[0];
    const float* ln1_w  = (const float*)d_in[1];
    const float* ln1_b  = (const float*)d_in[2];
    const float* qkv_w  = (const float*)d_in[3];
    const float* qkv_b  = (const float*)d_in[4];
    const float* proj_w = (const float*)d_in[5];
    const float* proj_b = (const float*)d_in[6];
    const float* ln2_w  = (const float*)d_in[7];
    const float* ln2_b  = (const float*)d_in[8];
    const float* fc1_w  = (const float*)d_in[9];
    const float* fc1_b  = (const float*)d_in[10];
    const float* fc2_w  = (const float*)d_in[11];
    const float* fc2_b  = (const float*)d_in[12];
    float* out = (float*)d_out;

    float *qkvf, *x1;
    bf16 *hh, *hl, *oh, *ol, *mh, *ml, *wh, *wl;
    cudaGetSymbolAddress((void**)&qkvf, g_qkv);
    cudaGetSymbolAddress((void**)&x1,   g_x1);
    cudaGetSymbolAddress((void**)&hh,   g_h_hi);
    cudaGetSymbolAddress((void**)&hl,   g_h_lo);
    cudaGetSymbolAddress((void**)&oh,   g_o_hi);
    cudaGetSymbolAddress((void**)&ol,   g_o_lo);
    cudaGetSymbolAddress((void**)&mh,   g_mid_hi);
    cudaGetSymbolAddress((void**)&ml,   g_mid_lo);
    cudaGetSymbolAddress((void**)&wh,   g_w_hi);
    cudaGetSymbolAddress((void**)&wl,   g_w_lo);

    const size_t OFF_QKV  = 0;
    const size_t OFF_PROJ = (size_t)3 * CDIM * CDIM;
    const size_t OFF_FC1  = OFF_PROJ + (size_t)CDIM * CDIM;
    const size_t OFF_FC2  = OFF_FC1 + (size_t)HDIM * CDIM;

    cudaFuncSetAttribute(gemm_tc<0>, cudaFuncAttributeMaxDynamicSharedMemorySize, SMEM_BYTES);
    cudaFuncSetAttribute(gemm_tc<1>, cudaFuncAttributeMaxDynamicSharedMemorySize, SMEM_BYTES);
    cudaFuncSetAttribute(gemm_tc<2>, cudaFuncAttributeMaxDynamicSharedMemorySize, SMEM_BYTES);

    split_kernel<<<(3*CDIM*CDIM)/1024, 256>>>(qkv_w,  wh+OFF_QKV,  wl+OFF_QKV,  3*CDIM*CDIM);
    split_kernel<<<(CDIM*CDIM)/1024,   256>>>(proj_w, wh+OFF_PROJ, wl+OFF_PROJ, CDIM*CDIM);
    split_kernel<<<(HDIM*CDIM)/1024,   256>>>(fc1_w,  wh+OFF_FC1,  wl+OFF_FC1,  HDIM*CDIM);
    split_kernel<<<(CDIM*HDIM)/1024,   256>>>(fc2_w,  wh+OFF_FC2,  wl+OFF_FC2,  CDIM*HDIM);

    const int gy = (ROWS + 127) / 128;   // 145

    ln_kernel<<<ROWS, 256>>>(x, ln1_w, ln1_b, hh, hl);
    gemm_tc<0><<<dim3(3*CDIM/128, gy), 256, SMEM_BYTES>>>(
        hh, hl, wh+OFF_QKV, wl+OFF_QKV, qkv_b, nullptr,
        qkvf, nullptr, nullptr, ROWS, 3*CDIM, CDIM);
    int smem = 4 * 64 * SMP * sizeof(float);
    cudaFuncSetAttribute(attn_kernel, cudaFuncAttributeMaxDynamicSharedMemorySize, smem);
    attn_kernel<<<dim3(BATCH * NHEADS, (SEQ + 63) / 64), 256, smem>>>(qkvf, oh, ol);
    gemm_tc<1><<<dim3(CDIM/128, gy), 256, SMEM_BYTES>>>(
        oh, ol, wh+OFF_PROJ, wl+OFF_PROJ, proj_b, x,
        x1, nullptr, nullptr, ROWS, CDIM, CDIM);
    ln_kernel<<<ROWS, 256>>>(x1, ln2_w, ln2_b, hh, hl);
    gemm_tc<2><<<dim3(HDIM/128, gy), 256, SMEM_BYTES>>>(
        hh, hl, wh+OFF_FC1, wl+OFF_FC1, fc1_b, nullptr,
        nullptr, mh, ml, ROWS, HDIM, CDIM);
    gemm_tc<1><<<dim3(CDIM/128, gy), 256, SMEM_BYTES>>>(
        mh, ml, wh+OFF_FC2, wl+OFF_FC2, fc2_b, x1,
        out, nullptr, nullptr, ROWS, CDIM, HDIM);
}

// round 11
// speedup vs baseline: 3.9742x; 1.7990x over previous
#include <cuda_runtime.h>
#include <cuda_fp16.h>
#include <math.h>
#include <stdint.h>

#define BATCH   32
#define SEQ     577
#define CDIM    1024
#define HDIM    4096
#define NHEADS  16
#define ROWS    (BATCH * SEQ)          // 18464

// ---------------- scratch ----------------------------------------------------
__device__ float  g_qkv[(size_t)ROWS * 3 * CDIM];
__device__ float  g_x1 [(size_t)ROWS * CDIM];
__device__ __half g_h  [(size_t)ROWS * CDIM];
__device__ __half g_o  [(size_t)ROWS * CDIM];
__device__ __half g_mid[(size_t)ROWS * HDIM];
#define NW_TOT (3*CDIM*CDIM + CDIM*CDIM + HDIM*CDIM + CDIM*HDIM)
__device__ __half g_w  [(size_t)NW_TOT];

// ---------------- weight convert fp32 -> fp16 --------------------------------
__global__ void cvt_kernel(const float* __restrict__ in,
                           __half* __restrict__ o, int n) {
    int i = (blockIdx.x * blockDim.x + threadIdx.x) * 4;
    if (i >= n) return;
    float4 v = *(const float4*)&in[i];
    __half2 a = __floats2half2_rn(v.x, v.y);
    __half2 b = __floats2half2_rn(v.z, v.w);
    *(__half2*)&o[i]     = a;
    *(__half2*)&o[i + 2] = b;
}

// ---------------- LayerNorm -> fp16 ------------------------------------------
__global__ void ln_kernel(const float* __restrict__ x,
                          const float* __restrict__ w,
                          const float* __restrict__ b,
                          __half* __restrict__ oh) {
    __shared__ float red[16];
    int row = blockIdx.x;
    int t = threadIdx.x;
    const float4* xr = (const float4*)(x + (size_t)row * CDIM);
    float4 v = xr[t];
    float s  = v.x + v.y + v.z + v.w;
    float ss = v.x*v.x + v.y*v.y + v.z*v.z + v.w*v.w;
    #pragma unroll
    for (int m = 16; m; m >>= 1) {
        s  += __shfl_xor_sync(0xffffffffu, s,  m);
        ss += __shfl_xor_sync(0xffffffffu, ss, m);
    }
    int warp = t >> 5;
    if ((t & 31) == 0) { red[warp] = s; red[warp + 8] = ss; }
    __syncthreads();
    s = 0.f; ss = 0.f;
    #pragma unroll
    for (int i = 0; i < 8; i++) { s += red[i]; ss += red[i + 8]; }
    float mean = s * (1.0f / CDIM);
    float var  = ss * (1.0f / CDIM) - mean * mean;
    float inv  = rsqrtf(var + 1e-6f);
    float4 wv = ((const float4*)w)[t];
    float4 bv = ((const float4*)b)[t];
    float o0 = (v.x - mean) * inv * wv.x + bv.x;
    float o1 = (v.y - mean) * inv * wv.y + bv.y;
    float o2 = (v.z - mean) * inv * wv.z + bv.z;
    float o3 = (v.w - mean) * inv * wv.w + bv.w;
    size_t off = (size_t)row * CDIM + t * 4;
    *(__half2*)&oh[off]     = __floats2half2_rn(o0, o1);
    *(__half2*)&oh[off + 2] = __floats2half2_rn(o2, o3);
}

// ---------------- tensor-core GEMM (fp16 mma.sync) ---------------------------
__device__ __forceinline__ unsigned smem_u32(const void* p) {
    return (unsigned)__cvta_generic_to_shared(p);
}
__device__ __forceinline__ void cp16(void* dst, const void* src) {
    asm volatile("cp.async.cg.shared.global [%0], [%1], 16;\n"
                 :: "r"(smem_u32(dst)), "l"(src));
}
__device__ __forceinline__ void ldm_x4(unsigned* r, unsigned addr) {
    asm volatile("ldmatrix.sync.aligned.m8n8.x4.shared.b16 {%0,%1,%2,%3}, [%4];\n"
                 : "=r"(r[0]), "=r"(r[1]), "=r"(r[2]), "=r"(r[3]) : "r"(addr));
}
__device__ __forceinline__ void mma16816(float* c, const unsigned* a, const unsigned* b) {
    asm volatile("mma.sync.aligned.m16n8k16.row.col.f32.f16.f16.f32 "
                 "{%0,%1,%2,%3},{%4,%5,%6,%7},{%8,%9},{%0,%1,%2,%3};\n"
                 : "+f"(c[0]), "+f"(c[1]), "+f"(c[2]), "+f"(c[3])
                 : "r"(a[0]), "r"(a[1]), "r"(a[2]), "r"(a[3]), "r"(b[0]), "r"(b[1]));
}

// K-tile 64: row = 64 fp16 + 8 pad = 72 elems (144B stride; 144%128=16 ->
// 8 successive rows hit 8 distinct 16B phases: ldmatrix conflict-free)
#define SPAD 72
#define TILE_ELE (128 * SPAD)                     // 9216 elems = 18432 B
#define SMEM_BYTES (4 * TILE_ELE * sizeof(__half)) // 73,728 B; 2 CTAs/SM fits

// C = A*B^T + epilogue. EPI: 0=+bias->f32, 1=+bias+res->f32, 2=+bias+GELU->fp16
template<int EPI>
__global__ __launch_bounds__(256, 2)
void gemm_tc(const __half* __restrict__ A, const __half* __restrict__ B,
             const float* __restrict__ bias, const float* __restrict__ res,
             float* __restrict__ C, __half* __restrict__ Ch,
             int M, int N, int K) {
    extern __shared__ __half smem[];
    int tid  = threadIdx.x;
    int lane = tid & 31;
    int warp = tid >> 5;
    int wm = warp >> 2;
    int wn = warp & 3;
    int bm = blockIdx.y * 128;
    int bn = blockIdx.x * 128;

    float c[4][4][4];
    #pragma unroll
    for (int i = 0; i < 4; i++)
        #pragma unroll
        for (int j = 0; j < 4; j++)
            #pragma unroll
            for (int r = 0; r < 4; r++) c[i][j][r] = 0.f;

    // stage st: A tile at (st*2+0), B tile at (st*2+1)
    auto issue = [&](int t, int st) {
        int k0 = t << 6;
        #pragma unroll
        for (int l = 0; l < 8; l++) {
            int arr = l >> 2;                      // 0=A, 1=B
            int local = tid + ((l & 3) << 8);      // 0..1023
            int r = local >> 3;
            int ch = local & 7;
            int gr = arr ? (bn + r) : min(bm + r, M - 1);
            const __half* src = (arr ? B : A) + (size_t)gr * K + k0 + ch * 8;
            __half* dst = smem + ((st << 1) + arr) * TILE_ELE + r * SPAD + ch * 8;
            cp16(dst, src);
        }
        asm volatile("cp.async.commit_group;\n");
    };

    int nT = K >> 6;
    issue(0, 0);

    for (int t = 0; t < nT; t++) {
        int st = t & 1;
        asm volatile("cp.async.wait_group 0;\n");
        __syncthreads();
        if (t + 1 < nT) issue(t + 1, st ^ 1);

        const __half* As = smem + ((st << 1) + 0) * TILE_ELE;
        const __half* Bs = smem + ((st << 1) + 1) * TILE_ELE;

        #pragma unroll
        for (int kk = 0; kk < 4; kk++) {
            int ki = kk << 4;
            unsigned bfr[4][2];
            #pragma unroll
            for (int jp = 0; jp < 2; jp++) {
                int brow = wn * 32 + jp * 16 + (((lane >> 4) & 1) << 3) + (lane & 7);
                int bcol = ki + (((lane >> 3) & 1) << 3);
                unsigned t4[4];
                ldm_x4(t4, smem_u32(Bs + brow * SPAD + bcol));
                bfr[2*jp][0] = t4[0]; bfr[2*jp][1] = t4[1];
                bfr[2*jp+1][0] = t4[2]; bfr[2*jp+1][1] = t4[3];
            }
            #pragma unroll
            for (int i = 0; i < 4; i++) {
                int arow = wm * 64 + i * 16 + (lane & 15);
                int acol = ki + ((lane >> 4) << 3);
                unsigned afr[4];
                ldm_x4(afr, smem_u32(As + arow * SPAD + acol));
                #pragma unroll
                for (int j = 0; j < 4; j++)
                    mma16816(c[i][j], afr, bfr[j]);
            }
        }
        __syncthreads();
    }

    // epilogue
    int g = lane >> 2, t2 = (lane & 3) << 1;
    #pragma unroll
    for (int i = 0; i < 4; i++) {
        #pragma unroll
        for (int j = 0; j < 4; j++) {
            int cc = bn + wn * 32 + j * 8 + t2;
            float2 bv = *(const float2*)&bias[cc];
            #pragma unroll
            for (int half = 0; half < 2; half++) {
                int gr = bm + wm * 64 + i * 16 + g + half * 8;
                if (gr < M) {
                    float vx = c[i][j][half * 2 + 0] + bv.x;
                    float vy = c[i][j][half * 2 + 1] + bv.y;
                    size_t off = (size_t)gr * N + cc;
                    if (EPI == 1) {
                        float2 rv = *(const float2*)&res[off];
                        vx += rv.x; vy += rv.y;
                    }
                    if (EPI == 2) {
                        vx = 0.5f * vx * (1.f + erff(vx * 0.70710678118654752f));
                        vy = 0.5f * vy * (1.f + erff(vy * 0.70710678118654752f));
                        *(__half2*)&Ch[off] = __floats2half2_rn(vx, vy);
                    } else {
                        *(float2*)&C[off] = make_float2(vx, vy);
                    }
                }
            }
        }
    }
}

// ---------------- fused attention (flash-style, fp32 SIMT) ------------------
#define SMP 68
__global__ __launch_bounds__(256)
void attn_kernel(const float* __restrict__ qkv, __half* __restrict__ ohp) {
    extern __shared__ float sm[];
    float* QsT = sm;
    float* KsT = sm + 64 * SMP;
    float* Vs  = sm + 2 * 64 * SMP;
    float* Ps  = sm + 3 * 64 * SMP;

    int bh = blockIdx.x;
    int b = bh >> 4, h = bh & 15;
    int q0 = blockIdx.y * 64;
    int tid = threadIdx.x;
    int tx = tid & 15, ty = tid >> 4;

    for (int i = tid; i < 1024; i += 256) {
        int r = i >> 4, d4 = (i & 15) * 4;
        int qr = q0 + r;
        float4 v = make_float4(0.f, 0.f, 0.f, 0.f);
        if (qr < SEQ)
            v = *(const float4*)&qkv[(size_t)(b * SEQ + qr) * 3072 + h * 64 + d4];
        QsT[(d4 + 0) * SMP + r] = v.x * 0.125f;
        QsT[(d4 + 1) * SMP + r] = v.y * 0.125f;
        QsT[(d4 + 2) * SMP + r] = v.z * 0.125f;
        QsT[(d4 + 3) * SMP + r] = v.w * 0.125f;
    }

    float m[4], l[4], acc[4][4];
    #pragma unroll
    for (int i = 0; i < 4; i++) {
        m[i] = -1e30f; l[i] = 0.f;
        #pragma unroll
        for (int j = 0; j < 4; j++) acc[i][j] = 0.f;
    }

    for (int kt = 0; kt < 10; kt++) {
        int k0 = kt * 64;
        __syncthreads();
        for (int i = tid; i < 1024; i += 256) {
            int cc = i >> 4, d4 = (i & 15) * 4;
            int kr = k0 + cc;
            float4 kv = make_float4(0.f, 0.f, 0.f, 0.f);
            float4 vv = make_float4(0.f, 0.f, 0.f, 0.f);
            if (kr < SEQ) {
                size_t base = (size_t)(b * SEQ + kr) * 3072 + h * 64 + d4;
                kv = *(const float4*)&qkv[base + 1024];
                vv = *(const float4*)&qkv[base + 2048];
            }
            KsT[(d4 + 0) * SMP + cc] = kv.x;
            KsT[(d4 + 1) * SMP + cc] = kv.y;
            KsT[(d4 + 2) * SMP + cc] = kv.z;
            KsT[(d4 + 3) * SMP + cc] = kv.w;
            *(float4*)&Vs[cc * SMP + d4] = vv;
        }
        __syncthreads();

        float s[4][4];
        #pragma unroll
        for (int i = 0; i < 4; i++)
            #pragma unroll
            for (int j = 0; j < 4; j++) s[i][j] = 0.f;
        #pragma unroll 8
        for (int d = 0; d < 64; d++) {
            float qa[4], ka[4];
            *(float4*)qa = *(float4*)&QsT[d * SMP + ty * 4];
            *(float4*)ka = *(float4*)&KsT[d * SMP + tx * 4];
            #pragma unroll
            for (int i = 0; i < 4; i++)
                #pragma unroll
                for (int j = 0; j < 4; j++)
                    s[i][j] += qa[i] * ka[j];
        }
        #pragma unroll
        for (int j = 0; j < 4; j++)
            if (k0 + tx * 4 + j >= SEQ) {
                #pragma unroll
                for (int i = 0; i < 4; i++) s[i][j] = -1e30f;
            }
        #pragma unroll
        for (int i = 0; i < 4; i++) {
            float mx = fmaxf(fmaxf(s[i][0], s[i][1]), fmaxf(s[i][2], s[i][3]));
            #pragma unroll
            for (int msk = 8; msk; msk >>= 1)
                mx = fmaxf(mx, __shfl_xor_sync(0xffffffffu, mx, msk));
            float mnew = fmaxf(m[i], mx);
            float f = __expf(m[i] - mnew);
            float rs = 0.f;
            #pragma unroll
            for (int j = 0; j < 4; j++) {
                s[i][j] = __expf(s[i][j] - mnew);
                rs += s[i][j];
            }
            #pragma unroll
            for (int msk = 8; msk; msk >>= 1)
                rs += __shfl_xor_sync(0xffffffffu, rs, msk);
            l[i] = l[i] * f + rs;
            m[i] = mnew;
            #pragma unroll
            for (int j = 0; j < 4; j++) acc[i][j] *= f;
            *(float4*)&Ps[(ty * 4 + i) * SMP + tx * 4] =
                make_float4(s[i][0], s[i][1], s[i][2], s[i][3]);
        }
        __syncthreads();
        #pragma unroll 8
        for (int cc = 0; cc < 64; cc++) {
            float pa[4], va[4];
            pa[0] = Ps[(ty * 4 + 0) * SMP + cc];
            pa[1] = Ps[(ty * 4 + 1) * SMP + cc];
            pa[2] = Ps[(ty * 4 + 2) * SMP + cc];
            pa[3] = Ps[(ty * 4 + 3) * SMP + cc];
            *(float4*)va = *(float4*)&Vs[cc * SMP + tx * 4];
            #pragma unroll
            for (int i = 0; i < 4; i++)
                #pragma unroll
                for (int j = 0; j < 4; j++)
                    acc[i][j] += pa[i] * va[j];
        }
    }

    #pragma unroll
    for (int i = 0; i < 4; i++) {
        int qr = q0 + ty * 4 + i;
        if (qr < SEQ) {
            float invl = 1.f / l[i];
            size_t off = (size_t)(b * SEQ + qr) * CDIM + h * 64 + tx * 4;
            *(__half2*)&ohp[off]     = __floats2half2_rn(acc[i][0]*invl, acc[i][1]*invl);
            *(__half2*)&ohp[off + 2] = __floats2half2_rn(acc[i][2]*invl, acc[i][3]*invl);
        }
    }
}

// ---------------- orchestration ---------------------------------------------
extern "C" void kernel_launch(void* const* d_in, const int* in_sizes, int n_in,
                              void* d_out, int out_size) {
    const float* x      = (const float*)d_in[0];
    const float* ln1_w  = (const float*)d_in[1];
    const float* ln1_b  = (const float*)d_in[2];
    const float* qkv_w  = (const float*)d_in[3];
    const float* qkv_b  = (const float*)d_in[4];
    const float* proj_w = (const float*)d_in[5];
    const float* proj_b = (const float*)d_in[6];
    const float* ln2_w  = (const float*)d_in[7];
    const float* ln2_b  = (const float*)d_in[8];
    const float* fc1_w  = (const float*)d_in[9];
    const float* fc1_b  = (const float*)d_in[10];
    const float* fc2_w  = (const float*)d_in[11];
    const float* fc2_b  = (const float*)d_in[12];
    float* out = (float*)d_out;

    float *qkvf, *x1;
    __half *hh, *oh, *mh, *wp;
    cudaGetSymbolAddress((void**)&qkvf, g_qkv);
    cudaGetSymbolAddress((void**)&x1,   g_x1);
    cudaGetSymbolAddress((void**)&hh,   g_h);
    cudaGetSymbolAddress((void**)&oh,   g_o);
    cudaGetSymbolAddress((void**)&mh,   g_mid);
    cudaGetSymbolAddress((void**)&wp,   g_w);

    const size_t OFF_QKV  = 0;
    const size_t OFF_PROJ = (size_t)3 * CDIM * CDIM;
    const size_t OFF_FC1  = OFF_PROJ + (size_t)CDIM * CDIM;
    const size_t OFF_FC2  = OFF_FC1 + (size_t)HDIM * CDIM;

    cudaFuncSetAttribute(gemm_tc<0>, cudaFuncAttributeMaxDynamicSharedMemorySize, SMEM_BYTES);
    cudaFuncSetAttribute(gemm_tc<1>, cudaFuncAttributeMaxDynamicSharedMemorySize, SMEM_BYTES);
    cudaFuncSetAttribute(gemm_tc<2>, cudaFuncAttributeMaxDynamicSharedMemorySize, SMEM_BYTES);

    cvt_kernel<<<(3*CDIM*CDIM)/1024, 256>>>(qkv_w,  wp+OFF_QKV,  3*CDIM*CDIM);
    cvt_kernel<<<(CDIM*CDIM)/1024,   256>>>(proj_w, wp+OFF_PROJ, CDIM*CDIM);
    cvt_kernel<<<(HDIM*CDIM)/1024,   256>>>(fc1_w,  wp+OFF_FC1,  HDIM*CDIM);
    cvt_kernel<<<(CDIM*HDIM)/1024,   256>>>(fc2_w,  wp+OFF_FC2,  CDIM*HDIM);

    const int gy = (ROWS + 127) / 128;   // 145

    ln_kernel<<<ROWS, 256>>>(x, ln1_w, ln1_b, hh);
    gemm_tc<0><<<dim3(3*CDIM/128, gy), 256, SMEM_BYTES>>>(
        hh, wp+OFF_QKV, qkv_b, nullptr, qkvf, nullptr, ROWS, 3*CDIM, CDIM);
    int smem = 4 * 64 * SMP * sizeof(float);
    cudaFuncSetAttribute(attn_kernel, cudaFuncAttributeMaxDynamicSharedMemorySize, smem);
    attn_kernel<<<dim3(BATCH * NHEADS, (SEQ + 63) / 64), 256, smem>>>(qkvf, oh);
    gemm_tc<1><<<dim3(CDIM/128, gy), 256, SMEM_BYTES>>>(
        oh, wp+OFF_PROJ, proj_b, x, x1, nullptr, ROWS, CDIM, CDIM);
    ln_kernel<<<ROWS, 256>>>(x1, ln2_w, ln2_b, hh);
    gemm_tc<2><<<dim3(HDIM/128, gy), 256, SMEM_BYTES>>>(
        hh, wp+OFF_FC1, fc1_b, nullptr, nullptr, mh, ROWS, HDIM, CDIM);
    gemm_tc<1><<<dim3(CDIM/128, gy), 256, SMEM_BYTES>>>(
        mh, wp+OFF_FC2, fc2_b, x1, out, nullptr, ROWS, CDIM, HDIM);
}

// round 17
// speedup vs baseline: 6.9827x; 1.7570x over previous
#include <cuda_runtime.h>
#include <cuda_fp16.h>
#include <math.h>
#include <stdint.h>

#define BATCH   32
#define SEQ     577
#define CDIM    1024
#define HDIM    4096
#define NHEADS  16
#define ROWS    (BATCH * SEQ)          // 18464

// ---------------- scratch ----------------------------------------------------
__device__ float  g_x1 [(size_t)ROWS * CDIM];
__device__ __half g_qkvh[(size_t)ROWS * 3 * CDIM];
__device__ __half g_h  [(size_t)ROWS * CDIM];
__device__ __half g_o  [(size_t)ROWS * CDIM];
__device__ __half g_mid[(size_t)ROWS * HDIM];
#define NW_TOT (3*CDIM*CDIM + CDIM*CDIM + HDIM*CDIM + CDIM*HDIM)
__device__ __half g_w  [(size_t)NW_TOT];

// ---------------- weight convert fp32 -> fp16 --------------------------------
__global__ void cvt_kernel(const float* __restrict__ in,
                           __half* __restrict__ o, int n) {
    int i = (blockIdx.x * blockDim.x + threadIdx.x) * 4;
    if (i >= n) return;
    float4 v = *(const float4*)&in[i];
    *(__half2*)&o[i]     = __floats2half2_rn(v.x, v.y);
    *(__half2*)&o[i + 2] = __floats2half2_rn(v.z, v.w);
}

// ---------------- LayerNorm -> fp16 ------------------------------------------
__global__ void ln_kernel(const float* __restrict__ x,
                          const float* __restrict__ w,
                          const float* __restrict__ b,
                          __half* __restrict__ oh) {
    __shared__ float red[16];
    int row = blockIdx.x;
    int t = threadIdx.x;
    const float4* xr = (const float4*)(x + (size_t)row * CDIM);
    float4 v = xr[t];
    float s  = v.x + v.y + v.z + v.w;
    float ss = v.x*v.x + v.y*v.y + v.z*v.z + v.w*v.w;
    #pragma unroll
    for (int m = 16; m; m >>= 1) {
        s  += __shfl_xor_sync(0xffffffffu, s,  m);
        ss += __shfl_xor_sync(0xffffffffu, ss, m);
    }
    int warp = t >> 5;
    if ((t & 31) == 0) { red[warp] = s; red[warp + 8] = ss; }
    __syncthreads();
    s = 0.f; ss = 0.f;
    #pragma unroll
    for (int i = 0; i < 8; i++) { s += red[i]; ss += red[i + 8]; }
    float mean = s * (1.0f / CDIM);
    float var  = ss * (1.0f / CDIM) - mean * mean;
    float inv  = rsqrtf(var + 1e-6f);
    float4 wv = ((const float4*)w)[t];
    float4 bv = ((const float4*)b)[t];
    float o0 = (v.x - mean) * inv * wv.x + bv.x;
    float o1 = (v.y - mean) * inv * wv.y + bv.y;
    float o2 = (v.z - mean) * inv * wv.z + bv.z;
    float o3 = (v.w - mean) * inv * wv.w + bv.w;
    size_t off = (size_t)row * CDIM + t * 4;
    *(__half2*)&oh[off]     = __floats2half2_rn(o0, o1);
    *(__half2*)&oh[off + 2] = __floats2half2_rn(o2, o3);
}

// ---------------- mma helpers -------------------------------------------------
__device__ __forceinline__ unsigned smem_u32(const void* p) {
    return (unsigned)__cvta_generic_to_shared(p);
}
__device__ __forceinline__ void cp16(void* dst, const void* src) {
    asm volatile("cp.async.cg.shared.global [%0], [%1], 16;\n"
                 :: "r"(smem_u32(dst)), "l"(src));
}
__device__ __forceinline__ void ldm_x4(unsigned* r, unsigned addr) {
    asm volatile("ldmatrix.sync.aligned.m8n8.x4.shared.b16 {%0,%1,%2,%3}, [%4];\n"
                 : "=r"(r[0]), "=r"(r[1]), "=r"(r[2]), "=r"(r[3]) : "r"(addr));
}
__device__ __forceinline__ void ldm_x4_t(unsigned* r, unsigned addr) {
    asm volatile("ldmatrix.sync.aligned.m8n8.x4.trans.shared.b16 {%0,%1,%2,%3}, [%4];\n"
                 : "=r"(r[0]), "=r"(r[1]), "=r"(r[2]), "=r"(r[3]) : "r"(addr));
}
__device__ __forceinline__ void mma16816(float* c, const unsigned* a, const unsigned* b) {
    asm volatile("mma.sync.aligned.m16n8k16.row.col.f32.f16.f16.f32 "
                 "{%0,%1,%2,%3},{%4,%5,%6,%7},{%8,%9},{%0,%1,%2,%3};\n"
                 : "+f"(c[0]), "+f"(c[1]), "+f"(c[2]), "+f"(c[3])
                 : "r"(a[0]), "r"(a[1]), "r"(a[2]), "r"(a[3]), "r"(b[0]), "r"(b[1]));
}

// ---------------- tensor-core GEMM -------------------------------------------
#define SPAD 72
#define TILE_ELE (128 * SPAD)
#define SMEM_BYTES (4 * TILE_ELE * sizeof(__half))

// EPI: 0=+bias->fp16, 1=+bias+res->f32, 2=+bias+GELU->fp16
template<int EPI>
__global__ __launch_bounds__(256, 2)
void gemm_tc(const __half* __restrict__ A, const __half* __restrict__ B,
             const float* __restrict__ bias, const float* __restrict__ res,
             float* __restrict__ C, __half* __restrict__ Ch,
             int M, int N, int K) {
    extern __shared__ __half smem[];
    int tid  = threadIdx.x;
    int lane = tid & 31;
    int warp = tid >> 5;
    int wm = warp >> 2;
    int wn = warp & 3;
    int bm = blockIdx.y * 128;
    int bn = blockIdx.x * 128;

    float c[4][4][4];
    #pragma unroll
    for (int i = 0; i < 4; i++)
        #pragma unroll
        for (int j = 0; j < 4; j++)
            #pragma unroll
            for (int r = 0; r < 4; r++) c[i][j][r] = 0.f;

    auto issue = [&](int t, int st) {
        int k0 = t << 6;
        #pragma unroll
        for (int l = 0; l < 8; l++) {
            int arr = l >> 2;
            int local = tid + ((l & 3) << 8);
            int r = local >> 3;
            int ch = local & 7;
            int gr = arr ? (bn + r) : min(bm + r, M - 1);
            const __half* src = (arr ? B : A) + (size_t)gr * K + k0 + ch * 8;
            __half* dst = smem + ((st << 1) + arr) * TILE_ELE + r * SPAD + ch * 8;
            cp16(dst, src);
        }
        asm volatile("cp.async.commit_group;\n");
    };

    int nT = K >> 6;
    issue(0, 0);

    for (int t = 0; t < nT; t++) {
        int st = t & 1;
        asm volatile("cp.async.wait_group 0;\n");
        __syncthreads();
        if (t + 1 < nT) issue(t + 1, st ^ 1);

        const __half* As = smem + ((st << 1) + 0) * TILE_ELE;
        const __half* Bs = smem + ((st << 1) + 1) * TILE_ELE;

        #pragma unroll
        for (int kk = 0; kk < 4; kk++) {
            int ki = kk << 4;
            unsigned bfr[4][2];
            #pragma unroll
            for (int jp = 0; jp < 2; jp++) {
                int brow = wn * 32 + jp * 16 + (((lane >> 4) & 1) << 3) + (lane & 7);
                int bcol = ki + (((lane >> 3) & 1) << 3);
                unsigned t4[4];
                ldm_x4(t4, smem_u32(Bs + brow * SPAD + bcol));
                bfr[2*jp][0] = t4[0]; bfr[2*jp][1] = t4[1];
                bfr[2*jp+1][0] = t4[2]; bfr[2*jp+1][1] = t4[3];
            }
            #pragma unroll
            for (int i = 0; i < 4; i++) {
                int arow = wm * 64 + i * 16 + (lane & 15);
                int acol = ki + ((lane >> 4) << 3);
                unsigned afr[4];
                ldm_x4(afr, smem_u32(As + arow * SPAD + acol));
                #pragma unroll
                for (int j = 0; j < 4; j++)
                    mma16816(c[i][j], afr, bfr[j]);
            }
        }
        __syncthreads();
    }

    int g = lane >> 2, t2 = (lane & 3) << 1;
    #pragma unroll
    for (int i = 0; i < 4; i++) {
        #pragma unroll
        for (int j = 0; j < 4; j++) {
            int cc = bn + wn * 32 + j * 8 + t2;
            float2 bv = *(const float2*)&bias[cc];
            #pragma unroll
            for (int half = 0; half < 2; half++) {
                int gr = bm + wm * 64 + i * 16 + g + half * 8;
                if (gr < M) {
                    float vx = c[i][j][half * 2 + 0] + bv.x;
                    float vy = c[i][j][half * 2 + 1] + bv.y;
                    size_t off = (size_t)gr * N + cc;
                    if (EPI == 1) {
                        float2 rv = *(const float2*)&res[off];
                        vx += rv.x; vy += rv.y;
                        *(float2*)&C[off] = make_float2(vx, vy);
                    } else if (EPI == 2) {
                        vx = 0.5f * vx * (1.f + erff(vx * 0.70710678118654752f));
                        vy = 0.5f * vy * (1.f + erff(vy * 0.70710678118654752f));
                        *(__half2*)&Ch[off] = __floats2half2_rn(vx, vy);
                    } else {
                        *(__half2*)&Ch[off] = __floats2half2_rn(vx, vy);
                    }
                }
            }
        }
    }
}

// ---------------- tensor-core attention --------------------------------------
// grid (B*H, 10), 128 threads (4 warps), warp owns 16 q-rows.
#define ASPAD 72
#define ATILE (64 * ASPAD)       // elems per 64x64 tile
// smem: Q | stage0{K,V} | stage1{K,V} = 5 tiles = 46080 B
#define ASMEM_BYTES (5 * ATILE * sizeof(__half))

__global__ __launch_bounds__(128)
void attn_tc(const __half* __restrict__ qkvh, __half* __restrict__ ohp) {
    extern __shared__ __half smem[];
    __half* Qs = smem;
    int bh = blockIdx.x;
    int b = bh >> 4, h = bh & 15;
    int q0 = blockIdx.y * 64;
    int tid = threadIdx.x;
    int lane = tid & 31;
    int warp = tid >> 5;

    // Q tile (guarded rows clamp)
    #pragma unroll
    for (int i = 0; i < 4; i++) {
        int local = tid + (i << 7);
        int r = local >> 3, ch = local & 7;
        int qr = min(q0 + r, SEQ - 1);
        cp16(Qs + r * ASPAD + ch * 8,
             qkvh + (size_t)(b * SEQ + qr) * 3072 + h * 64 + ch * 8);
    }
    auto issue_kv = [&](int kt, int st) {
        int k0 = kt * 64;
        __half* Ks = smem + ATILE + st * 2 * ATILE;
        __half* Vs = Ks + ATILE;
        #pragma unroll
        for (int i = 0; i < 4; i++) {
            int local = tid + (i << 7);
            int r = local >> 3, ch = local & 7;
            int kr = min(k0 + r, SEQ - 1);
            size_t base = (size_t)(b * SEQ + kr) * 3072 + h * 64 + ch * 8;
            cp16(Ks + r * ASPAD + ch * 8, qkvh + base + 1024);
            cp16(Vs + r * ASPAD + ch * 8, qkvh + base + 2048);
        }
        asm volatile("cp.async.commit_group;\n");
    };
    issue_kv(0, 0);

    float m0 = -1e30f, m1 = -1e30f, l0 = 0.f, l1 = 0.f;
    float oc[8][4];
    #pragma unroll
    for (int j = 0; j < 8; j++)
        #pragma unroll
        for (int r = 0; r < 4; r++) oc[j][r] = 0.f;

    int g = lane >> 2, tq = lane & 3;

    for (int kt = 0; kt < 10; kt++) {
        int st = kt & 1;
        asm volatile("cp.async.wait_group 0;\n");
        __syncthreads();
        if (kt + 1 < 10) issue_kv(kt + 1, st ^ 1);

        const __half* Ks = smem + ATILE + st * 2 * ATILE;
        const __half* Vs = Ks + ATILE;

        // ---- S = Q K^T (fp32 accum) ----
        float sc[8][4];
        #pragma unroll
        for (int j = 0; j < 8; j++)
            #pragma unroll
            for (int r = 0; r < 4; r++) sc[j][r] = 0.f;
        #pragma unroll
        for (int kk = 0; kk < 4; kk++) {
            int ki = kk << 4;
            unsigned afr[4];
            ldm_x4(afr, smem_u32(Qs + (warp * 16 + (lane & 15)) * ASPAD
                                 + ki + ((lane >> 4) << 3)));
            #pragma unroll
            for (int jb = 0; jb < 4; jb++) {
                int brow = jb * 16 + (((lane >> 4) & 1) << 3) + (lane & 7);
                int bcol = ki + (((lane >> 3) & 1) << 3);
                unsigned t4[4];
                ldm_x4(t4, smem_u32(Ks + brow * ASPAD + bcol));
                unsigned b0[2] = {t4[0], t4[1]}, b1[2] = {t4[2], t4[3]};
                mma16816(sc[2*jb],     afr, b0);
                mma16816(sc[2*jb + 1], afr, b1);
            }
        }
        // scale + mask
        #pragma unroll
        for (int j = 0; j < 8; j++) {
            int cg = kt * 64 + j * 8 + tq * 2;
            #pragma unroll
            for (int r = 0; r < 4; r++) sc[j][r] *= 0.125f;
            if (cg     >= SEQ) { sc[j][0] = -1e30f; sc[j][2] = -1e30f; }
            if (cg + 1 >= SEQ) { sc[j][1] = -1e30f; sc[j][3] = -1e30f; }
        }
        // ---- online softmax ----
        float mx0 = -1e30f, mx1 = -1e30f;
        #pragma unroll
        for (int j = 0; j < 8; j++) {
            mx0 = fmaxf(mx0, fmaxf(sc[j][0], sc[j][1]));
            mx1 = fmaxf(mx1, fmaxf(sc[j][2], sc[j][3]));
        }
        mx0 = fmaxf(mx0, __shfl_xor_sync(0xffffffffu, mx0, 1));
        mx0 = fmaxf(mx0, __shfl_xor_sync(0xffffffffu, mx0, 2));
        mx1 = fmaxf(mx1, __shfl_xor_sync(0xffffffffu, mx1, 1));
        mx1 = fmaxf(mx1, __shfl_xor_sync(0xffffffffu, mx1, 2));
        float mn0 = fmaxf(m0, mx0), mn1 = fmaxf(m1, mx1);
        float f0 = __expf(m0 - mn0), f1 = __expf(m1 - mn1);
        unsigned pa[8], pb[8];
        float s0 = 0.f, s1 = 0.f;
        #pragma unroll
        for (int j = 0; j < 8; j++) {
            float e0 = __expf(sc[j][0] - mn0);
            float e1 = __expf(sc[j][1] - mn0);
            float e2 = __expf(sc[j][2] - mn1);
            float e3 = __expf(sc[j][3] - mn1);
            s0 += e0 + e1; s1 += e2 + e3;
            __half2 ha = __floats2half2_rn(e0, e1);
            __half2 hb = __floats2half2_rn(e2, e3);
            pa[j] = *(unsigned*)&ha;
            pb[j] = *(unsigned*)&hb;
        }
        s0 += __shfl_xor_sync(0xffffffffu, s0, 1);
        s0 += __shfl_xor_sync(0xffffffffu, s0, 2);
        s1 += __shfl_xor_sync(0xffffffffu, s1, 1);
        s1 += __shfl_xor_sync(0xffffffffu, s1, 2);
        l0 = l0 * f0 + s0; l1 = l1 * f1 + s1;
        m0 = mn0; m1 = mn1;
        #pragma unroll
        for (int j = 0; j < 8; j++) {
            oc[j][0] *= f0; oc[j][1] *= f0;
            oc[j][2] *= f1; oc[j][3] *= f1;
        }
        // ---- O += P V ----
        #pragma unroll
        for (int kk = 0; kk < 4; kk++) {
            unsigned afr[4] = {pa[2*kk], pb[2*kk], pa[2*kk + 1], pb[2*kk + 1]};
            #pragma unroll
            for (int jb = 0; jb < 4; jb++) {
                int krow = kk * 16 + (((lane >> 3) & 1) << 3) + (lane & 7);
                int ncol = jb * 16 + (((lane >> 4) & 1) << 3);
                unsigned t4[4];
                ldm_x4_t(t4, smem_u32(Vs + krow * ASPAD + ncol));
                unsigned b0[2] = {t4[0], t4[1]}, b1[2] = {t4[2], t4[3]};
                mma16816(oc[2*jb],     afr, b0);
                mma16816(oc[2*jb + 1], afr, b1);
            }
        }
        __syncthreads();
    }

    // ---- write O ----
    float i0 = 1.f / l0, i1 = 1.f / l1;
    int qr0 = q0 + warp * 16 + g;
    #pragma unroll
    for (int j = 0; j < 8; j++) {
        int cc = h * 64 + j * 8 + tq * 2;
        if (qr0 < SEQ)
            *(__half2*)&ohp[(size_t)(b * SEQ + qr0) * CDIM + cc] =
                __floats2half2_rn(oc[j][0] * i0, oc[j][1] * i0);
        if (qr0 + 8 < SEQ)
            *(__half2*)&ohp[(size_t)(b * SEQ + qr0 + 8) * CDIM + cc] =
                __floats2half2_rn(oc[j][2] * i1, oc[j][3] * i1);
    }
}

// ---------------- orchestration ---------------------------------------------
extern "C" void kernel_launch(void* const* d_in, const int* in_sizes, int n_in,
                              void* d_out, int out_size) {
    const float* x      = (const float*)d_in[0];
    const float* ln1_w  = (const float*)d_in[1];
    const float* ln1_b  = (const float*)d_in[2];
    const float* qkv_w  = (const float*)d_in[3];
    const float* qkv_b  = (const float*)d_in[4];
    const float* proj_w = (const float*)d_in[5];
    const float* proj_b = (const float*)d_in[6];
    const float* ln2_w  = (const float*)d_in[7];
    const float* ln2_b  = (const float*)d_in[8];
    const float* fc1_w  = (const float*)d_in[9];
    const float* fc1_b  = (const float*)d_in[10];
    const float* fc2_w  = (const float*)d_in[11];
    const float* fc2_b  = (const float*)d_in[12];
    float* out = (float*)d_out;

    float *x1;
    __half *qkvh, *hh, *oh, *mh, *wp;
    cudaGetSymbolAddress((void**)&x1,   g_x1);
    cudaGetSymbolAddress((void**)&qkvh, g_qkvh);
    cudaGetSymbolAddress((void**)&hh,   g_h);
    cudaGetSymbolAddress((void**)&oh,   g_o);
    cudaGetSymbolAddress((void**)&mh,   g_mid);
    cudaGetSymbolAddress((void**)&wp,   g_w);

    const size_t OFF_QKV  = 0;
    const size_t OFF_PROJ = (size_t)3 * CDIM * CDIM;
    const size_t OFF_FC1  = OFF_PROJ + (size_t)CDIM * CDIM;
    const size_t OFF_FC2  = OFF_FC1 + (size_t)HDIM * CDIM;

    cudaFuncSetAttribute(gemm_tc<0>, cudaFuncAttributeMaxDynamicSharedMemorySize, SMEM_BYTES);
    cudaFuncSetAttribute(gemm_tc<1>, cudaFuncAttributeMaxDynamicSharedMemorySize, SMEM_BYTES);
    cudaFuncSetAttribute(gemm_tc<2>, cudaFuncAttributeMaxDynamicSharedMemorySize, SMEM_BYTES);
    cudaFuncSetAttribute(attn_tc,    cudaFuncAttributeMaxDynamicSharedMemorySize, ASMEM_BYTES);

    cvt_kernel<<<(3*CDIM*CDIM)/1024, 256>>>(qkv_w,  wp+OFF_QKV,  3*CDIM*CDIM);
    cvt_kernel<<<(CDIM*CDIM)/1024,   256>>>(proj_w, wp+OFF_PROJ, CDIM*CDIM);
    cvt_kernel<<<(HDIM*CDIM)/1024,   256>>>(fc1_w,  wp+OFF_FC1,  HDIM*CDIM);
    cvt_kernel<<<(CDIM*HDIM)/1024,   256>>>(fc2_w,  wp+OFF_FC2,  CDIM*HDIM);

    const int gy = (ROWS + 127) / 128;   // 145

    ln_kernel<<<ROWS, 256>>>(x, ln1_w, ln1_b, hh);
    gemm_tc<0><<<dim3(3*CDIM/128, gy), 256, SMEM_BYTES>>>(
        hh, wp+OFF_QKV, qkv_b, nullptr, nullptr, qkvh, ROWS, 3*CDIM, CDIM);
    attn_tc<<<dim3(BATCH * NHEADS, (SEQ + 63) / 64), 128, ASMEM_BYTES>>>(qkvh, oh);
    gemm_tc<1><<<dim3(CDIM/128, gy), 256, SMEM_BYTES>>>(
        oh, wp+OFF_PROJ, proj_b, x, x1, nullptr, ROWS, CDIM, CDIM);
    ln_kernel<<<ROWS, 256>>>(x1, ln2_w, ln2_b, hh);
    gemm_tc<2><<<dim3(HDIM/128, gy), 256, SMEM_BYTES>>>(
        hh, wp+OFF_FC1, fc1_b, nullptr, nullptr, mh, ROWS, HDIM, CDIM);
    gemm_tc<1><<<dim3(CDIM/128, gy), 256, SMEM_BYTES>>>(
        mh, wp+OFF_FC2, fc2_b, x1, out, nullptr, ROWS, CDIM, HDIM);
}